// round 10
// baseline (speedup 1.0000x reference)
#include <cuda_runtime.h>
#include <cuda_bf16.h>
#include <cstdint>

#define B_   4
#define CI_  128
#define CO_  128
#define H_   128
#define W_   128
#define HW_  (H_*W_)
#define KK_  9
#define NPIX (B_*HW_)   // 65536
#define BN_EPS 0.001f

// ---------------- scratch ----------------
__device__ float  g_x_nhwc[NPIX*CI_];                          // [b][h][w][ci]
__device__ float  g_off[NPIX*18];                              // [px][18]
__device__ __align__(16) __nv_bfloat16 g_wb_hi[KK_*CO_*CI_];   // [tap][co][ci]
__device__ __align__(16) __nv_bfloat16 g_wb_lo[KK_*CO_*CI_];
__device__ __align__(16) __nv_bfloat16 g_wo_hi[KK_*32*CI_];    // offset conv w
__device__ __align__(16) __nv_bfloat16 g_wo_lo[KK_*32*CI_];
__device__ float  g_out[NPIX*CO_];                             // [px][co]
__device__ double g_sum[CO_];
__device__ double g_sumsq[CO_];
__device__ float  g_scale[CO_];
__device__ float  g_shift[CO_];

__device__ __forceinline__ uint32_t smem_u32(const void* p) {
    uint32_t a;
    asm("{ .reg .u64 t; cvta.to.shared.u64 t, %1; cvt.u32.u64 %0, t; }" : "=r"(a) : "l"(p));
    return a;
}
__device__ __forceinline__ void ldm_x4(uint32_t* r, uint32_t a) {
    asm volatile("ldmatrix.sync.aligned.m8n8.x4.shared.b16 {%0,%1,%2,%3}, [%4];"
                 : "=r"(r[0]), "=r"(r[1]), "=r"(r[2]), "=r"(r[3]) : "r"(a));
}
__device__ __forceinline__ void mma_bf16(float* c, const uint32_t* a, const uint32_t* b) {
    asm volatile(
        "mma.sync.aligned.m16n8k16.row.col.f32.bf16.bf16.f32 "
        "{%0,%1,%2,%3}, {%4,%5,%6,%7}, {%8,%9}, {%0,%1,%2,%3};"
        : "+f"(c[0]), "+f"(c[1]), "+f"(c[2]), "+f"(c[3])
        : "r"(a[0]), "r"(a[1]), "r"(a[2]), "r"(a[3]), "r"(b[0]), "r"(b[1]));
}
__device__ __forceinline__ void bf16_split(float v, uint16_t& h, uint16_t& l) {
    __nv_bfloat16 hb = __float2bfloat16(v);
    __nv_bfloat16 lb = __float2bfloat16(v - __bfloat162float(hb));
    h = __bfloat16_as_ushort(hb);
    l = __bfloat16_as_ushort(lb);
}
__device__ __forceinline__ uint32_t prmt_hi(uint32_t a, uint32_t b) {
    uint32_t d;
    asm("prmt.b32 %0, %1, %2, 0x7632;" : "=r"(d) : "r"(a), "r"(b));
    return d;
}
__device__ __forceinline__ void split4(float4 s, uint2& hp, uint2& lp) {
    uint32_t u0 = __float_as_uint(s.x), u1 = __float_as_uint(s.y);
    uint32_t u2 = __float_as_uint(s.z), u3 = __float_as_uint(s.w);
    hp.x = prmt_hi(u0, u1);
    hp.y = prmt_hi(u2, u3);
    float l0 = s.x - __uint_as_float(u0 & 0xFFFF0000u);
    float l1 = s.y - __uint_as_float(u1 & 0xFFFF0000u);
    float l2 = s.z - __uint_as_float(u2 & 0xFFFF0000u);
    float l3 = s.w - __uint_as_float(u3 & 0xFFFF0000u);
    lp.x = prmt_hi(__float_as_uint(l0), __float_as_uint(l1));
    lp.y = prmt_hi(__float_as_uint(l2), __float_as_uint(l3));
}
__device__ __forceinline__ void cp16(uint32_t dst, const void* src) {
    asm volatile("cp.async.cg.shared.global [%0], [%1], 16;" :: "r"(dst), "l"(src));
}
__device__ __forceinline__ void cp_commit() { asm volatile("cp.async.commit_group;" ::: "memory"); }
__device__ __forceinline__ void cp_wait0()  { asm volatile("cp.async.wait_group 0;" ::: "memory"); }
#define BAR_SYNC(id)   asm volatile("bar.sync %0, 384;"   :: "r"(id) : "memory")
#define BAR_ARRIVE(id) asm volatile("bar.arrive %0, 384;" :: "r"(id) : "memory")

// ---------------- x: NCHW -> NHWC ----------------
__global__ void k_tr_x(const float* __restrict__ x) {
    __shared__ float sm[32][33];
    int b = blockIdx.z, ci0 = blockIdx.y * 32, hw0 = blockIdx.x * 32;
    int tx = threadIdx.x, ty = threadIdx.y;
#pragma unroll
    for (int i = 0; i < 4; ++i) {
        int ci = ci0 + ty + i * 8;
        sm[ty + i * 8][tx] = x[(b * CI_ + ci) * HW_ + hw0 + tx];
    }
    __syncthreads();
#pragma unroll
    for (int i = 0; i < 4; ++i) {
        int hw = hw0 + ty + i * 8;
        g_x_nhwc[(b * HW_ + hw) * CI_ + ci0 + tx] = sm[tx][ty + i * 8];
    }
}

// ---------------- prep: BN zero + both weight transforms ----------------
__global__ void k_prep(const float* __restrict__ w_dcn, const float* __restrict__ w_off) {
    int idx = blockIdx.x * 256 + threadIdx.x;
    if (idx < 128) { g_sum[idx] = 0.0; g_sumsq[idx] = 0.0; }
    if (idx < KK_ * CO_ * CI_) {
        int tap = idx >> 14;
        int r   = idx & 16383;
        int co  = r >> 7;
        int ci  = r & 127;
        float w = w_dcn[(co * CI_ + ci) * KK_ + tap];
        uint16_t h, l;
        bf16_split(w, h, l);
        g_wb_hi[idx] = __ushort_as_bfloat16(h);
        g_wb_lo[idx] = __ushort_as_bfloat16(l);
    }
    if (idx < KK_ * 32 * CI_) {
        int tap = idx >> 12;
        int r   = idx & 4095;
        int co  = r >> 7;
        int ci  = r & 127;
        float w = (co < 18) ? w_off[(co * CI_ + ci) * KK_ + tap] : 0.f;
        uint16_t h, l;
        bf16_split(w, h, l);
        g_wo_hi[idx] = __ushort_as_bfloat16(h);
        g_wo_lo[idx] = __ushort_as_bfloat16(l);
    }
}

#define RS 272   // padded stride for k_offT only

// ---------------- offset conv, tensorized (unchanged) ----------------
#define OFF_AHI 0
#define OFF_ALO 34816
#define OFF_BHI 69632
#define OFF_BLO 78336
#define OFF_TOT 87040

__global__ void __launch_bounds__(256, 2) k_offT(const float* __restrict__ b_off) {
    extern __shared__ char sb[];
    uint32_t sbase = smem_u32(sb);
    int tid = threadIdx.x;
    int wid = tid >> 5, lid = tid & 31;
    int px0 = blockIdx.x * 128;

    float acc[4][4];
#pragma unroll
    for (int ni = 0; ni < 4; ++ni)
#pragma unroll
        for (int j = 0; j < 4; ++j) acc[ni][j] = 0.f;

    uint32_t a_lane = (uint32_t)(wid * 16 + (lid & 15)) * RS + ((lid >> 4) << 4);
    uint32_t b_lane4 = (uint32_t)((lid & 7) | ((lid >> 4) << 3)) * RS + (((lid >> 3) & 1) << 4);

    for (int k = 0; k < 9; ++k) {
        int ky = k / 3, kx = k - ky * 3;
        __syncthreads();
#pragma unroll
        for (int t = 0; t < 2; ++t) {
            int e = tid + t * 256;
            int row = e >> 4, c16 = e & 15;
            *(uint4*)(sb + OFF_BHI + row * RS + c16 * 16) =
                *(const uint4*)(g_wo_hi + k * 4096 + row * 128 + c16 * 8);
            *(uint4*)(sb + OFF_BLO + row * RS + c16 * 16) =
                *(const uint4*)(g_wo_lo + k * 4096 + row * 128 + c16 * 8);
        }
#pragma unroll 2
        for (int i = 0; i < 16; ++i) {
            int p = i * 8 + wid;
            int px = px0 + p;
            int b = px >> 14, h = (px >> 7) & 127, w = px & 127;
            int y = h - 1 + ky, xx = w - 1 + kx;
            uint2 hp = make_uint2(0u, 0u), lp = make_uint2(0u, 0u);
            if ((unsigned)y < (unsigned)H_ && (unsigned)xx < (unsigned)W_) {
                float4 v = *(const float4*)(g_x_nhwc + ((b * H_ + y) * W_ + xx) * CI_ + lid * 4);
                split4(v, hp, lp);
            }
            uint32_t off = (uint32_t)p * RS + (uint32_t)lid * 8;
            *(uint2*)(sb + OFF_AHI + off) = hp;
            *(uint2*)(sb + OFF_ALO + off) = lp;
        }
        __syncthreads();
#pragma unroll
        for (int ks = 0; ks < 8; ++ks) {
            uint32_t kb = (uint32_t)ks * 32;
            uint32_t ah[4], al[4], bh4[2][4], bl4[2][4];
            ldm_x4(ah, sbase + OFF_AHI + a_lane + kb);
            ldm_x4(al, sbase + OFF_ALO + a_lane + kb);
#pragma unroll
            for (int ni2 = 0; ni2 < 2; ++ni2) {
                uint32_t ba = b_lane4 + (uint32_t)(ni2 * 16) * RS + kb;
                ldm_x4(bh4[ni2], sbase + OFF_BHI + ba);
                ldm_x4(bl4[ni2], sbase + OFF_BLO + ba);
            }
#pragma unroll
            for (int ni2 = 0; ni2 < 2; ++ni2)
#pragma unroll
                for (int half = 0; half < 2; ++half)
                    mma_bf16(acc[ni2 * 2 + half], ah, bh4[ni2] + half * 2);
#pragma unroll
            for (int ni2 = 0; ni2 < 2; ++ni2)
#pragma unroll
                for (int half = 0; half < 2; ++half)
                    mma_bf16(acc[ni2 * 2 + half], ah, bl4[ni2] + half * 2);
#pragma unroll
            for (int ni2 = 0; ni2 < 2; ++ni2)
#pragma unroll
                for (int half = 0; half < 2; ++half)
                    mma_bf16(acc[ni2 * 2 + half], al, bh4[ni2] + half * 2);
        }
    }
    int rofs = lid >> 2, cofs = (lid & 3) * 2;
    int r0 = px0 + wid * 16 + rofs;
#pragma unroll
    for (int ni = 0; ni < 4; ++ni) {
        int c = ni * 8 + cofs;
        if (c < 18) {
            float2 bo = *(const float2*)(b_off + c);
            *(float2*)(g_off + r0 * 18 + c) =
                make_float2(acc[ni][0] + bo.x, acc[ni][1] + bo.y);
            *(float2*)(g_off + (r0 + 8) * 18 + c) =
                make_float2(acc[ni][2] + bo.x, acc[ni][3] + bo.y);
        }
    }
}

// ---------------- main: warp-specialized, 384 threads (8 cons + 4 prod) -------
// smem (XOR-swizzled 256B rows): A stages 2x64KB, Bhi 2x32KB, Blo 1x32KB = 224KB
// barriers: A_FULL 1,2  A_FREE 3,4  BLO_FULL 5  BLO_FREE 6
#define A_ST(s)   ((uint32_t)(s) * 65536u)
#define A_LOOFF   32768u
#define BHI_ST(s) (131072u + (uint32_t)(s) * 32768u)
#define BLO_ST    196608u
#define WS_TOT    229376
#define RSF       132

struct Samp {
    float4 v00, v01, v10, v11;
    float w00, w01, w10, w11;
    uint32_t off;
};

__device__ __forceinline__ void samp_issueP(Samp& S, int p, int t, int ky, int kx,
                                            int px0, int lid) {
    int px = px0 + p;
    int b = px >> 14, h = (px >> 7) & 127, w = px & 127;
    float2 d = *(const float2*)(g_off + px * 18 + 2 * t);
    float ysf = (float)(h - 1 + ky) + d.x;
    float xsf = (float)(w - 1 + kx) + d.y;
    float fy = floorf(ysf), fx = floorf(xsf);
    float wy = ysf - fy, wx = xsf - fx;
    int iy0 = (int)fy, ix0 = (int)fx;
    int iy1 = iy0 + 1, ix1 = ix0 + 1;
    float my0 = (iy0 >= 0 && iy0 < H_) ? 1.f : 0.f;
    float my1 = (iy1 >= 0 && iy1 < H_) ? 1.f : 0.f;
    float mx0 = (ix0 >= 0 && ix0 < W_) ? 1.f : 0.f;
    float mx1 = (ix1 >= 0 && ix1 < W_) ? 1.f : 0.f;
    int cy0 = min(H_ - 1, max(0, iy0)), cy1 = min(H_ - 1, max(0, iy1));
    int cx0 = min(W_ - 1, max(0, ix0)), cx1 = min(W_ - 1, max(0, ix1));
    int base = b * HW_;
    int c4 = lid * 4;
    S.v00 = *(const float4*)(g_x_nhwc + (base + cy0 * W_ + cx0) * CI_ + c4);
    S.v01 = *(const float4*)(g_x_nhwc + (base + cy0 * W_ + cx1) * CI_ + c4);
    S.v10 = *(const float4*)(g_x_nhwc + (base + cy1 * W_ + cx0) * CI_ + c4);
    S.v11 = *(const float4*)(g_x_nhwc + (base + cy1 * W_ + cx1) * CI_ + c4);
    S.w00 = (1.f - wy) * (1.f - wx) * my0 * mx0;
    S.w01 = (1.f - wy) * wx * my0 * mx1;
    S.w10 = wy * (1.f - wx) * my1 * mx0;
    S.w11 = wy * wx * my1 * mx1;
    S.off = (uint32_t)p * 256u + (((((uint32_t)lid >> 1) ^ ((uint32_t)p & 7u)) << 4) | (((uint32_t)lid & 1u) << 3));
}

__device__ __forceinline__ void samp_storeP(char* sb, uint32_t abase, const Samp& S) {
    float4 s;
    s.x = fmaf(S.v11.x, S.w11, fmaf(S.v10.x, S.w10, fmaf(S.v01.x, S.w01, S.v00.x * S.w00)));
    s.y = fmaf(S.v11.y, S.w11, fmaf(S.v10.y, S.w10, fmaf(S.v01.y, S.w01, S.v00.y * S.w00)));
    s.z = fmaf(S.v11.z, S.w11, fmaf(S.v10.z, S.w10, fmaf(S.v01.z, S.w01, S.v00.z * S.w00)));
    s.w = fmaf(S.v11.w, S.w11, fmaf(S.v10.w, S.w10, fmaf(S.v01.w, S.w01, S.v00.w * S.w00)));
    uint2 hp, lp;
    split4(s, hp, lp);
    *(uint2*)(sb + abase + S.off) = hp;
    *(uint2*)(sb + abase + A_LOOFF + S.off) = lp;
}

// swizzled cp.async of one 32KB B tile (2048 chunks, 128 producer threads -> 16 each)
__device__ __forceinline__ void copy_B_swz(uint32_t dstbase, const char* src, int ptid) {
#pragma unroll
    for (int j = 0; j < 16; ++j) {
        int c = ptid + j * 128;
        uint32_t row = (uint32_t)(c >> 4), c16 = (uint32_t)(c & 15);
        uint32_t dof = row * 256u + ((c16 ^ (row & 7u)) << 4);
        cp16(dstbase + dof, src + c * 16);
    }
}

__global__ void __launch_bounds__(384, 1) k_mainWS() {
    extern __shared__ char sb[];
    uint32_t sbase = smem_u32(sb);
    int tid = threadIdx.x;
    int wid = tid >> 5, lid = tid & 31;
    int px0 = blockIdx.x * 128;

    float acc[2][8][4];
#pragma unroll
    for (int mi = 0; mi < 2; ++mi)
#pragma unroll
        for (int nf = 0; nf < 8; ++nf)
#pragma unroll
            for (int j = 0; j < 4; ++j) acc[mi][nf][j] = 0.f;

    if (wid < 8) {
        // ================= CONSUMER (R8 structure) =================
        int mw = wid >> 1, nw = wid & 1;
        uint32_t rA[2], rA7[2];
#pragma unroll
        for (int mi = 0; mi < 2; ++mi) {
            uint32_t r = (uint32_t)(mw * 32 + mi * 16 + (lid & 15));
            rA[mi] = r * 256u; rA7[mi] = r & 7u;
        }
        uint32_t chAh = (uint32_t)(lid >> 4);
        uint32_t rowp = (uint32_t)((lid & 7) | ((lid >> 4) << 3));
        uint32_t chBh = (uint32_t)((lid >> 3) & 1);
        uint32_t rB[4], rB7[4];
#pragma unroll
        for (int n = 0; n < 4; ++n) {
            uint32_t r = (uint32_t)(nw * 64 + n * 16) + rowp;
            rB[n] = r * 256u; rB7[n] = r & 7u;
        }

        for (int k = 0; k < 9; ++k) {
            int st = k & 1;
            BAR_SYNC(1 + st);     // A[k] + Bhi[k] ready
            BAR_SYNC(5);          // Blo[k] ready
            uint32_t Ast = sbase + A_ST(st);
            uint32_t Bh  = sbase + BHI_ST(st);
            uint32_t Bl  = sbase + BLO_ST;
#pragma unroll
            for (int s = 0; s < 8; ++s) {
                uint32_t cA = (uint32_t)(2 * s) + chAh;
                uint32_t cB = (uint32_t)(2 * s) + chBh;
                uint32_t ah[2][4], bh[4][4], bl[4][4];
#pragma unroll
                for (int mi = 0; mi < 2; ++mi)
                    ldm_x4(ah[mi], Ast + rA[mi] + ((cA ^ rA7[mi]) << 4));
#pragma unroll
                for (int n = 0; n < 4; ++n)
                    ldm_x4(bh[n], Bh + rB[n] + ((cB ^ rB7[n]) << 4));
#pragma unroll
                for (int n = 0; n < 4; ++n)
                    ldm_x4(bl[n], Bl + rB[n] + ((cB ^ rB7[n]) << 4));
                // pass hh
#pragma unroll
                for (int mi = 0; mi < 2; ++mi)
#pragma unroll
                    for (int nf = 0; nf < 8; ++nf)
                        mma_bf16(acc[mi][nf], ah[mi], bh[nf >> 1] + (nf & 1) * 2);
                // pass hl
#pragma unroll
                for (int mi = 0; mi < 2; ++mi)
#pragma unroll
                    for (int nf = 0; nf < 8; ++nf)
                        mma_bf16(acc[mi][nf], ah[mi], bl[nf >> 1] + (nf & 1) * 2);
                // pass lh (al loaded late)
                uint32_t al[2][4];
#pragma unroll
                for (int mi = 0; mi < 2; ++mi)
                    ldm_x4(al[mi], Ast + A_LOOFF + rA[mi] + ((cA ^ rA7[mi]) << 4));
#pragma unroll
                for (int mi = 0; mi < 2; ++mi)
#pragma unroll
                    for (int nf = 0; nf < 8; ++nf)
                        mma_bf16(acc[mi][nf], al[mi], bh[nf >> 1] + (nf & 1) * 2);
            }
            BAR_ARRIVE(6);             // Blo free
            BAR_ARRIVE(3 + st);        // A + Bhi stage free
        }
    } else {
        // ================= PRODUCER (4 warps, 32 px each) =================
        int wp = wid - 8;
        int ptid = wp * 32 + lid;
        for (int k = 0; k < 9; ++k) {
            int st = k & 1;
            if (k >= 2) BAR_SYNC(3 + st);  // A + Bhi stage free
            copy_B_swz(sbase + BHI_ST(st), (const char*)g_wb_hi + k * 32768, ptid);
            if (k >= 1) BAR_SYNC(6);       // Blo buffer free
            copy_B_swz(sbase + BLO_ST, (const char*)g_wb_lo + k * 32768, ptid);
            cp_commit();
            int ky = k / 3, kx = k - ky * 3;
            uint32_t Ast = A_ST(st);
            Samp S[3];
            samp_issueP(S[0], wp,     k, ky, kx, px0, lid);
            samp_issueP(S[1], 4 + wp, k, ky, kx, px0, lid);
            samp_issueP(S[2], 8 + wp, k, ky, kx, px0, lid);
#pragma unroll
            for (int i = 0; i < 32; ++i) {
                samp_storeP(sb, Ast, S[i % 3]);
                if (i + 3 < 32)
                    samp_issueP(S[i % 3], (i + 3) * 4 + wp, k, ky, kx, px0, lid);
            }
            cp_wait0();
            __threadfence_block();
            BAR_ARRIVE(1 + st);            // A[k] + Bhi[k] full
            BAR_ARRIVE(5);                 // Blo[k] full
        }
    }

    __syncthreads();
    // ---- epilogue: consumers stage acc, all 384 store + BN partials ----
    float* stg = (float*)sb;
    if (wid < 8) {
        int mw = wid >> 1, nw = wid & 1;
        int rofs = lid >> 2, cofs = (lid & 3) * 2;
#pragma unroll
        for (int mi = 0; mi < 2; ++mi) {
            int r0 = mw * 32 + mi * 16 + rofs;
#pragma unroll
            for (int nf = 0; nf < 8; ++nf) {
                int co = nw * 64 + nf * 8 + cofs;
                *(float2*)(stg + r0 * RSF + co)       = make_float2(acc[mi][nf][0], acc[mi][nf][1]);
                *(float2*)(stg + (r0 + 8) * RSF + co) = make_float2(acc[mi][nf][2], acc[mi][nf][3]);
            }
        }
    }
    __syncthreads();
    for (int idx = tid; idx < 4096; idx += 384) {
        int row = idx >> 5, c4 = (idx & 31) * 4;
        float4 v = *(const float4*)(stg + row * RSF + c4);
        *(float4*)(g_out + (px0 + row) * CO_ + c4) = v;
    }
    if (tid < 256) {
        int co = tid & 127, q = tid >> 7;       // 2 halves x 64 rows
        float s = 0.f, qq = 0.f;
#pragma unroll
        for (int r = 0; r < 64; ++r) {
            float v = stg[(q * 64 + r) * RSF + co];
            s += v; qq = fmaf(v, v, qq);
        }
        float* reds = (float*)(sb + BHI_ST(0));
        float* redq = reds + 256;
        reds[q * 128 + co] = s;
        redq[q * 128 + co] = qq;
    }
    __syncthreads();
    if (tid < 128) {
        float* reds = (float*)(sb + BHI_ST(0));
        float* redq = reds + 256;
        atomicAdd(&g_sum[tid],   (double)(reds[tid] + reds[128 + tid]));
        atomicAdd(&g_sumsq[tid], (double)(redq[tid] + redq[128 + tid]));
    }
}

// ---------------- BN finalize ----------------
__global__ void k_fin(const float* __restrict__ gamma, const float* __restrict__ beta) {
    int c = threadIdx.x;
    if (c < CO_) {
        double N = (double)NPIX;
        double mean = g_sum[c] / N;
        double var  = g_sumsq[c] / N - mean * mean;
        float a = gamma[c] * rsqrtf((float)var + BN_EPS);
        g_scale[c] = a;
        g_shift[c] = beta[c] - (float)mean * a;
    }
}

// ---------------- apply BN + ReLU + transpose [px][co] -> NCHW ----------------
__global__ void k_apply(float* __restrict__ out) {
    __shared__ float sm[32][33];
    int b = blockIdx.z, co0 = blockIdx.y * 32, hw0 = blockIdx.x * 32;
    int tx = threadIdx.x, ty = threadIdx.y;
#pragma unroll
    for (int i = 0; i < 4; ++i) {
        int hw = hw0 + ty + i * 8;
        sm[ty + i * 8][tx] = g_out[(b * HW_ + hw) * CO_ + co0 + tx];
    }
    __syncthreads();
#pragma unroll
    for (int i = 0; i < 4; ++i) {
        int co = co0 + ty + i * 8;
        float a = g_scale[co], sh = g_shift[co];
        float v = fmaf(sm[tx][ty + i * 8], a, sh);
        out[(b * CO_ + co) * HW_ + hw0 + tx] = fmaxf(v, 0.f);
    }
}

// ---------------- launch ----------------
extern "C" void kernel_launch(void* const* d_in, const int* in_sizes, int n_in,
                              void* d_out, int out_size) {
    const float* x      = (const float*)d_in[0];
    const float* w_off  = (const float*)d_in[1];
    const float* b_off  = (const float*)d_in[2];
    const float* w_dcn  = (const float*)d_in[3];
    const float* gamma  = (const float*)d_in[4];
    const float* beta   = (const float*)d_in[5];
    float* out = (float*)d_out;

    cudaFuncSetAttribute(k_offT,   cudaFuncAttributeMaxDynamicSharedMemorySize, OFF_TOT);
    cudaFuncSetAttribute(k_mainWS, cudaFuncAttributeMaxDynamicSharedMemorySize, WS_TOT);

    dim3 tb(32, 8);
    k_tr_x<<<dim3(512, 4, B_), tb>>>(x);          // launch 0
    k_prep<<<576, 256>>>(w_dcn, w_off);           // launch 1
    k_offT<<<512, 256, OFF_TOT>>>(b_off);         // launch 2
    k_mainWS<<<512, 384, WS_TOT>>>();             // launch 3  <- ncu capture slot
    k_fin<<<1, 128>>>(gamma, beta);               // launch 4
    k_apply<<<dim3(512, 4, B_), tb>>>(out);       // launch 5
}

// round 11
// speedup vs baseline: 1.1586x; 1.1586x over previous
#include <cuda_runtime.h>
#include <cuda_fp16.h>
#include <cstdint>

#define B_   4
#define CI_  128
#define CO_  128
#define H_   128
#define W_   128
#define HW_  (H_*W_)
#define KK_  9
#define NPIX (B_*HW_)   // 65536
#define BN_EPS 0.001f

// ---------------- scratch ----------------
__device__ float  g_x_nhwc[NPIX*CI_];                       // [b][h][w][ci]
__device__ float  g_off[NPIX*18];                           // [px][18]
__device__ __align__(16) __half g_wb_hi[KK_*CO_*CI_];       // [tap][co][ci] fp16 hi
__device__ __align__(16) __half g_wb_lo[KK_*CO_*CI_];       // fp16 lo
__device__ __align__(16) __half g_wo_hi[KK_*32*CI_];        // offset conv w
__device__ __align__(16) __half g_wo_lo[KK_*32*CI_];
__device__ float  g_out[NPIX*CO_];                          // [px][co]
__device__ double g_sum[CO_];
__device__ double g_sumsq[CO_];
__device__ float  g_scale[CO_];
__device__ float  g_shift[CO_];

__device__ __forceinline__ uint32_t smem_u32(const void* p) {
    uint32_t a;
    asm("{ .reg .u64 t; cvta.to.shared.u64 t, %1; cvt.u32.u64 %0, t; }" : "=r"(a) : "l"(p));
    return a;
}
__device__ __forceinline__ void ldm_x4(uint32_t* r, uint32_t a) {
    asm volatile("ldmatrix.sync.aligned.m8n8.x4.shared.b16 {%0,%1,%2,%3}, [%4];"
                 : "=r"(r[0]), "=r"(r[1]), "=r"(r[2]), "=r"(r[3]) : "r"(a));
}
__device__ __forceinline__ void mma_f16(float* c, const uint32_t* a, const uint32_t* b) {
    asm volatile(
        "mma.sync.aligned.m16n8k16.row.col.f32.f16.f16.f32 "
        "{%0,%1,%2,%3}, {%4,%5,%6,%7}, {%8,%9}, {%0,%1,%2,%3};"
        : "+f"(c[0]), "+f"(c[1]), "+f"(c[2]), "+f"(c[3])
        : "r"(a[0]), "r"(a[1]), "r"(a[2]), "r"(a[3]), "r"(b[0]), "r"(b[1]));
}
// pack two floats -> f16x2 (lo in low half)
__device__ __forceinline__ uint32_t f16x2(float lo, float hi) {
    uint32_t d;
    asm("cvt.rn.f16x2.f32 %0, %1, %2;" : "=r"(d) : "f"(hi), "f"(lo));
    return d;
}
__device__ __forceinline__ void cp16(uint32_t dst, const void* src) {
    asm volatile("cp.async.cg.shared.global [%0], [%1], 16;" :: "r"(dst), "l"(src));
}
__device__ __forceinline__ void cp_commit() { asm volatile("cp.async.commit_group;" ::: "memory"); }
__device__ __forceinline__ void cp_wait0()  { asm volatile("cp.async.wait_group 0;" ::: "memory"); }
#define BAR_SYNC(id)   asm volatile("bar.sync %0, 512;"   :: "r"(id) : "memory")
#define BAR_ARRIVE(id) asm volatile("bar.arrive %0, 512;" :: "r"(id) : "memory")

// ---------------- x: NCHW -> NHWC ----------------
__global__ void k_tr_x(const float* __restrict__ x) {
    __shared__ float sm[32][33];
    int b = blockIdx.z, ci0 = blockIdx.y * 32, hw0 = blockIdx.x * 32;
    int tx = threadIdx.x, ty = threadIdx.y;
#pragma unroll
    for (int i = 0; i < 4; ++i) {
        int ci = ci0 + ty + i * 8;
        sm[ty + i * 8][tx] = x[(b * CI_ + ci) * HW_ + hw0 + tx];
    }
    __syncthreads();
#pragma unroll
    for (int i = 0; i < 4; ++i) {
        int hw = hw0 + ty + i * 8;
        g_x_nhwc[(b * HW_ + hw) * CI_ + ci0 + tx] = sm[tx][ty + i * 8];
    }
}

// ---------------- prep: BN zero + both weight transforms (fp16 hi/lo) ---------
__global__ void k_prep(const float* __restrict__ w_dcn, const float* __restrict__ w_off) {
    int idx = blockIdx.x * 256 + threadIdx.x;
    if (idx < 128) { g_sum[idx] = 0.0; g_sumsq[idx] = 0.0; }
    if (idx < KK_ * CO_ * CI_) {
        int tap = idx >> 14;
        int r   = idx & 16383;
        int co  = r >> 7;
        int ci  = r & 127;
        float w = w_dcn[(co * CI_ + ci) * KK_ + tap];
        __half hi = __float2half_rn(w);
        __half lo = __float2half_rn(w - __half2float(hi));
        g_wb_hi[idx] = hi;
        g_wb_lo[idx] = lo;
    }
    if (idx < KK_ * 32 * CI_) {
        int tap = idx >> 12;
        int r   = idx & 4095;
        int co  = r >> 7;
        int ci  = r & 127;
        float w = (co < 18) ? w_off[(co * CI_ + ci) * KK_ + tap] : 0.f;
        __half hi = __float2half_rn(w);
        __half lo = __float2half_rn(w - __half2float(hi));
        g_wo_hi[idx] = hi;
        g_wo_lo[idx] = lo;
    }
}

#define RS 272   // padded stride for k_offT

// ---------------- offset conv, tensorized fp16 2-pass ----------------
#define OFF_A   0
#define OFF_BHI 34816
#define OFF_BLO 43520
#define OFF_TOT 52224

__global__ void __launch_bounds__(256, 2) k_offT(const float* __restrict__ b_off) {
    extern __shared__ char sb[];
    uint32_t sbase = smem_u32(sb);
    int tid = threadIdx.x;
    int wid = tid >> 5, lid = tid & 31;
    int px0 = blockIdx.x * 128;

    float acc[4][4];
#pragma unroll
    for (int ni = 0; ni < 4; ++ni)
#pragma unroll
        for (int j = 0; j < 4; ++j) acc[ni][j] = 0.f;

    uint32_t a_lane = (uint32_t)(wid * 16 + (lid & 15)) * RS + ((lid >> 4) << 4);
    uint32_t b_lane4 = (uint32_t)((lid & 7) | ((lid >> 4) << 3)) * RS + (((lid >> 3) & 1) << 4);

    for (int k = 0; k < 9; ++k) {
        int ky = k / 3, kx = k - ky * 3;
        __syncthreads();
#pragma unroll
        for (int t = 0; t < 2; ++t) {
            int e = tid + t * 256;
            int row = e >> 4, c16 = e & 15;
            *(uint4*)(sb + OFF_BHI + row * RS + c16 * 16) =
                *(const uint4*)(g_wo_hi + k * 4096 + row * 128 + c16 * 8);
            *(uint4*)(sb + OFF_BLO + row * RS + c16 * 16) =
                *(const uint4*)(g_wo_lo + k * 4096 + row * 128 + c16 * 8);
        }
#pragma unroll 2
        for (int i = 0; i < 16; ++i) {
            int p = i * 8 + wid;
            int px = px0 + p;
            int b = px >> 14, h = (px >> 7) & 127, w = px & 127;
            int y = h - 1 + ky, xx = w - 1 + kx;
            uint2 hp = make_uint2(0u, 0u);
            if ((unsigned)y < (unsigned)H_ && (unsigned)xx < (unsigned)W_) {
                float4 v = *(const float4*)(g_x_nhwc + ((b * H_ + y) * W_ + xx) * CI_ + lid * 4);
                hp.x = f16x2(v.x, v.y);
                hp.y = f16x2(v.z, v.w);
            }
            *(uint2*)(sb + OFF_A + (uint32_t)p * RS + (uint32_t)lid * 8) = hp;
        }
        __syncthreads();
#pragma unroll
        for (int ks = 0; ks < 8; ++ks) {
            uint32_t kb = (uint32_t)ks * 32;
            uint32_t ah[4], b4[2][4];
            ldm_x4(ah, sbase + OFF_A + a_lane + kb);
#pragma unroll
            for (int ni2 = 0; ni2 < 2; ++ni2)
                ldm_x4(b4[ni2], sbase + OFF_BHI + b_lane4 + (uint32_t)(ni2 * 16) * RS + kb);
#pragma unroll
            for (int ni2 = 0; ni2 < 2; ++ni2)
#pragma unroll
                for (int half = 0; half < 2; ++half)
                    mma_f16(acc[ni2 * 2 + half], ah, b4[ni2] + half * 2);
#pragma unroll
            for (int ni2 = 0; ni2 < 2; ++ni2)
                ldm_x4(b4[ni2], sbase + OFF_BLO + b_lane4 + (uint32_t)(ni2 * 16) * RS + kb);
#pragma unroll
            for (int ni2 = 0; ni2 < 2; ++ni2)
#pragma unroll
                for (int half = 0; half < 2; ++half)
                    mma_f16(acc[ni2 * 2 + half], ah, b4[ni2] + half * 2);
        }
    }
    int rofs = lid >> 2, cofs = (lid & 3) * 2;
    int r0 = px0 + wid * 16 + rofs;
#pragma unroll
    for (int ni = 0; ni < 4; ++ni) {
        int c = ni * 8 + cofs;
        if (c < 18) {
            float2 bo = *(const float2*)(b_off + c);
            *(float2*)(g_off + r0 * 18 + c) =
                make_float2(acc[ni][0] + bo.x, acc[ni][1] + bo.y);
            *(float2*)(g_off + (r0 + 8) * 18 + c) =
                make_float2(acc[ni][2] + bo.x, acc[ni][3] + bo.y);
        }
    }
}

// ---------------- main: warp-specialized fp16 2-pass, 512 thr (8+8) -----------
// smem (XOR-swizzled 256B rows): A 2x32KB, Bhi 2x32KB, Blo 2x32KB = 192KB
// barriers: FULL 1,2  FREE 3,4
#define A_ST(s)   ((uint32_t)(s) * 32768u)
#define BHI_ST(s) (65536u + (uint32_t)(s) * 32768u)
#define BLO_ST(s) (131072u + (uint32_t)(s) * 32768u)
#define WS_TOT    196608
#define RSF       132

struct Samp {
    float4 v00, v01, v10, v11;
    float w00, w01, w10, w11;
    uint32_t off;
};

__device__ __forceinline__ void samp_issueP(Samp& S, int p, int t, int ky, int kx,
                                            int px0, int lid) {
    int px = px0 + p;
    int b = px >> 14, h = (px >> 7) & 127, w = px & 127;
    float2 d = *(const float2*)(g_off + px * 18 + 2 * t);
    float ysf = (float)(h - 1 + ky) + d.x;
    float xsf = (float)(w - 1 + kx) + d.y;
    float fy = floorf(ysf), fx = floorf(xsf);
    float wy = ysf - fy, wx = xsf - fx;
    int iy0 = (int)fy, ix0 = (int)fx;
    int iy1 = iy0 + 1, ix1 = ix0 + 1;
    float my0 = (iy0 >= 0 && iy0 < H_) ? 1.f : 0.f;
    float my1 = (iy1 >= 0 && iy1 < H_) ? 1.f : 0.f;
    float mx0 = (ix0 >= 0 && ix0 < W_) ? 1.f : 0.f;
    float mx1 = (ix1 >= 0 && ix1 < W_) ? 1.f : 0.f;
    int cy0 = min(H_ - 1, max(0, iy0)), cy1 = min(H_ - 1, max(0, iy1));
    int cx0 = min(W_ - 1, max(0, ix0)), cx1 = min(W_ - 1, max(0, ix1));
    int base = b * HW_;
    int c4 = lid * 4;
    S.v00 = *(const float4*)(g_x_nhwc + (base + cy0 * W_ + cx0) * CI_ + c4);
    S.v01 = *(const float4*)(g_x_nhwc + (base + cy0 * W_ + cx1) * CI_ + c4);
    S.v10 = *(const float4*)(g_x_nhwc + (base + cy1 * W_ + cx0) * CI_ + c4);
    S.v11 = *(const float4*)(g_x_nhwc + (base + cy1 * W_ + cx1) * CI_ + c4);
    S.w00 = (1.f - wy) * (1.f - wx) * my0 * mx0;
    S.w01 = (1.f - wy) * wx * my0 * mx1;
    S.w10 = wy * (1.f - wx) * my1 * mx0;
    S.w11 = wy * wx * my1 * mx1;
    S.off = (uint32_t)p * 256u + (((((uint32_t)lid >> 1) ^ ((uint32_t)p & 7u)) << 4) | (((uint32_t)lid & 1u) << 3));
}

__device__ __forceinline__ void samp_storeP(char* sb, uint32_t abase, const Samp& S) {
    float4 s;
    s.x = fmaf(S.v11.x, S.w11, fmaf(S.v10.x, S.w10, fmaf(S.v01.x, S.w01, S.v00.x * S.w00)));
    s.y = fmaf(S.v11.y, S.w11, fmaf(S.v10.y, S.w10, fmaf(S.v01.y, S.w01, S.v00.y * S.w00)));
    s.z = fmaf(S.v11.z, S.w11, fmaf(S.v10.z, S.w10, fmaf(S.v01.z, S.w01, S.v00.z * S.w00)));
    s.w = fmaf(S.v11.w, S.w11, fmaf(S.v10.w, S.w10, fmaf(S.v01.w, S.w01, S.v00.w * S.w00)));
    uint2 hp;
    hp.x = f16x2(s.x, s.y);
    hp.y = f16x2(s.z, s.w);
    *(uint2*)(sb + abase + S.off) = hp;
}

// swizzled cp.async of one 32KB B tile (2048 chunks, 256 producer threads)
__device__ __forceinline__ void copy_B_swz(uint32_t dstbase, const char* src, int ptid) {
#pragma unroll
    for (int j = 0; j < 8; ++j) {
        int c = ptid + j * 256;
        uint32_t row = (uint32_t)(c >> 4), c16 = (uint32_t)(c & 15);
        uint32_t dof = row * 256u + ((c16 ^ (row & 7u)) << 4);
        cp16(dstbase + dof, src + c * 16);
    }
}

__global__ void __launch_bounds__(512, 1) k_mainWS() {
    extern __shared__ char sb[];
    uint32_t sbase = smem_u32(sb);
    int tid = threadIdx.x;
    int wid = tid >> 5, lid = tid & 31;
    int px0 = blockIdx.x * 128;

    float acc[2][8][4];
#pragma unroll
    for (int mi = 0; mi < 2; ++mi)
#pragma unroll
        for (int nf = 0; nf < 8; ++nf)
#pragma unroll
            for (int j = 0; j < 4; ++j) acc[mi][nf][j] = 0.f;

    if (wid < 8) {
        // ================= CONSUMER =================
        int mw = wid >> 1, nw = wid & 1;
        uint32_t rA[2], rA7[2];
#pragma unroll
        for (int mi = 0; mi < 2; ++mi) {
            uint32_t r = (uint32_t)(mw * 32 + mi * 16 + (lid & 15));
            rA[mi] = r * 256u; rA7[mi] = r & 7u;
        }
        uint32_t chAh = (uint32_t)(lid >> 4);
        uint32_t rowp = (uint32_t)((lid & 7) | ((lid >> 4) << 3));
        uint32_t chBh = (uint32_t)((lid >> 3) & 1);
        uint32_t rB[4], rB7[4];
#pragma unroll
        for (int n = 0; n < 4; ++n) {
            uint32_t r = (uint32_t)(nw * 64 + n * 16) + rowp;
            rB[n] = r * 256u; rB7[n] = r & 7u;
        }

        for (int k = 0; k < 9; ++k) {
            int st = k & 1;
            BAR_SYNC(1 + st);     // A[k] + B[k] ready
            uint32_t Ast = sbase + A_ST(st);
            uint32_t Bh  = sbase + BHI_ST(st);
            uint32_t Bl  = sbase + BLO_ST(st);
#pragma unroll
            for (int s = 0; s < 8; ++s) {
                uint32_t cA = (uint32_t)(2 * s) + chAh;
                uint32_t cB = (uint32_t)(2 * s) + chBh;
                uint32_t ah[2][4], b4[4][4];
#pragma unroll
                for (int mi = 0; mi < 2; ++mi)
                    ldm_x4(ah[mi], Ast + rA[mi] + ((cA ^ rA7[mi]) << 4));
                // pass hi: A * Bh
#pragma unroll
                for (int n = 0; n < 4; ++n)
                    ldm_x4(b4[n], Bh + rB[n] + ((cB ^ rB7[n]) << 4));
#pragma unroll
                for (int mi = 0; mi < 2; ++mi)
#pragma unroll
                    for (int nf = 0; nf < 8; ++nf)
                        mma_f16(acc[mi][nf], ah[mi], b4[nf >> 1] + (nf & 1) * 2);
                // pass lo: A * Bl (reuse b4 regs)
#pragma unroll
                for (int n = 0; n < 4; ++n)
                    ldm_x4(b4[n], Bl + rB[n] + ((cB ^ rB7[n]) << 4));
#pragma unroll
                for (int mi = 0; mi < 2; ++mi)
#pragma unroll
                    for (int nf = 0; nf < 8; ++nf)
                        mma_f16(acc[mi][nf], ah[mi], b4[nf >> 1] + (nf & 1) * 2);
            }
            BAR_ARRIVE(3 + st);   // stage free
        }
    } else {
        // ================= PRODUCER =================
        int wp = wid - 8;
        int ptid = wp * 32 + lid;
        for (int k = 0; k < 9; ++k) {
            int st = k & 1;
            if (k >= 2) BAR_SYNC(3 + st);  // stage free
            copy_B_swz(sbase + BHI_ST(st), (const char*)g_wb_hi + k * 32768, ptid);
            copy_B_swz(sbase + BLO_ST(st), (const char*)g_wb_lo + k * 32768, ptid);
            cp_commit();
            int ky = k / 3, kx = k - ky * 3;
            uint32_t Ast = A_ST(st);
            Samp S[3];
            samp_issueP(S[0], wp,      k, ky, kx, px0, lid);
            samp_issueP(S[1], 8 + wp,  k, ky, kx, px0, lid);
            samp_issueP(S[2], 16 + wp, k, ky, kx, px0, lid);
#pragma unroll
            for (int i = 0; i < 16; ++i) {
                samp_storeP(sb, Ast, S[i % 3]);
                if (i + 3 < 16)
                    samp_issueP(S[i % 3], (i + 3) * 8 + wp, k, ky, kx, px0, lid);
            }
            cp_wait0();
            __threadfence_block();
            BAR_ARRIVE(1 + st);            // A[k] + B[k] full
        }
    }

    __syncthreads();
    // ---- epilogue: consumers stage acc, all store + BN partials ----
    float* stg = (float*)sb;
    if (wid < 8) {
        int mw = wid >> 1, nw = wid & 1;
        int rofs = lid >> 2, cofs = (lid & 3) * 2;
#pragma unroll
        for (int mi = 0; mi < 2; ++mi) {
            int r0 = mw * 32 + mi * 16 + rofs;
#pragma unroll
            for (int nf = 0; nf < 8; ++nf) {
                int co = nw * 64 + nf * 8 + cofs;
                *(float2*)(stg + r0 * RSF + co)       = make_float2(acc[mi][nf][0], acc[mi][nf][1]);
                *(float2*)(stg + (r0 + 8) * RSF + co) = make_float2(acc[mi][nf][2], acc[mi][nf][3]);
            }
        }
    }
    __syncthreads();
#pragma unroll
    for (int tt = 0; tt < 8; ++tt) {
        int idx = tid + tt * 512;
        int row = idx >> 5, c4 = (idx & 31) * 4;
        float4 v = *(const float4*)(stg + row * RSF + c4);
        *(float4*)(g_out + (px0 + row) * CO_ + c4) = v;
    }
    {
        int co = tid & 127, q = tid >> 7;
        float s = 0.f, qq = 0.f;
#pragma unroll
        for (int r = 0; r < 32; ++r) {
            float v = stg[(q * 32 + r) * RSF + co];
            s += v; qq = fmaf(v, v, qq);
        }
        float* reds = (float*)(sb + BLO_ST(0));
        float* redq = reds + 512;
        reds[q * 128 + co] = s;
        redq[q * 128 + co] = qq;
        __syncthreads();
        if (tid < 128) {
            float ss = reds[tid] + reds[128 + tid] + reds[256 + tid] + reds[384 + tid];
            float sq = redq[tid] + redq[128 + tid] + redq[256 + tid] + redq[384 + tid];
            atomicAdd(&g_sum[tid], (double)ss);
            atomicAdd(&g_sumsq[tid], (double)sq);
        }
    }
}

// ---------------- BN finalize ----------------
__global__ void k_fin(const float* __restrict__ gamma, const float* __restrict__ beta) {
    int c = threadIdx.x;
    if (c < CO_) {
        double N = (double)NPIX;
        double mean = g_sum[c] / N;
        double var  = g_sumsq[c] / N - mean * mean;
        float a = gamma[c] * rsqrtf((float)var + BN_EPS);
        g_scale[c] = a;
        g_shift[c] = beta[c] - (float)mean * a;
    }
}

// ---------------- apply BN + ReLU + transpose [px][co] -> NCHW ----------------
__global__ void k_apply(float* __restrict__ out) {
    __shared__ float sm[32][33];
    int b = blockIdx.z, co0 = blockIdx.y * 32, hw0 = blockIdx.x * 32;
    int tx = threadIdx.x, ty = threadIdx.y;
#pragma unroll
    for (int i = 0; i < 4; ++i) {
        int hw = hw0 + ty + i * 8;
        sm[ty + i * 8][tx] = g_out[(b * HW_ + hw) * CO_ + co0 + tx];
    }
    __syncthreads();
#pragma unroll
    for (int i = 0; i < 4; ++i) {
        int co = co0 + ty + i * 8;
        float a = g_scale[co], sh = g_shift[co];
        float v = fmaf(sm[tx][ty + i * 8], a, sh);
        out[(b * CO_ + co) * HW_ + hw0 + tx] = fmaxf(v, 0.f);
    }
}

// ---------------- launch ----------------
extern "C" void kernel_launch(void* const* d_in, const int* in_sizes, int n_in,
                              void* d_out, int out_size) {
    const float* x      = (const float*)d_in[0];
    const float* w_off  = (const float*)d_in[1];
    const float* b_off  = (const float*)d_in[2];
    const float* w_dcn  = (const float*)d_in[3];
    const float* gamma  = (const float*)d_in[4];
    const float* beta   = (const float*)d_in[5];
    float* out = (float*)d_out;

    cudaFuncSetAttribute(k_offT,   cudaFuncAttributeMaxDynamicSharedMemorySize, OFF_TOT);
    cudaFuncSetAttribute(k_mainWS, cudaFuncAttributeMaxDynamicSharedMemorySize, WS_TOT);

    dim3 tb(32, 8);
    k_tr_x<<<dim3(512, 4, B_), tb>>>(x);          // launch 0
    k_prep<<<576, 256>>>(w_dcn, w_off);           // launch 1
    k_offT<<<512, 256, OFF_TOT>>>(b_off);         // launch 2
    k_mainWS<<<512, 512, WS_TOT>>>();             // launch 3  <- ncu capture slot
    k_fin<<<1, 128>>>(gamma, beta);               // launch 4
    k_apply<<<dim3(512, 4, B_), tb>>>(out);       // launch 5
}

// round 12
// speedup vs baseline: 1.4418x; 1.2444x over previous
#include <cuda_runtime.h>
#include <cuda_bf16.h>
#include <cuda_fp16.h>
#include <cstdint>

#define B_   4
#define CI_  128
#define CO_  128
#define H_   128
#define W_   128
#define HW_  (H_*W_)
#define KK_  9
#define NPIX (B_*HW_)   // 65536
#define BN_EPS 0.001f

// ---------------- scratch ----------------
__device__ float  g_x_nhwc[NPIX*CI_];                          // [b][h][w][ci]
__device__ float  g_off[NPIX*18];                              // [px][18]
__device__ __align__(16) __nv_bfloat16 g_wb_hi[KK_*CO_*CI_];   // main w bf16 hi
__device__ __align__(16) __nv_bfloat16 g_wb_lo[KK_*CO_*CI_];   // main w bf16 lo
__device__ __align__(16) __half g_wo_hi[KK_*32*CI_];           // offT w fp16 hi
__device__ __align__(16) __half g_wo_lo[KK_*32*CI_];           // offT w fp16 lo
__device__ float  g_out[NPIX*CO_];                             // [px][co]
__device__ double g_sum[CO_];
__device__ double g_sumsq[CO_];
__device__ float  g_scale[CO_];
__device__ float  g_shift[CO_];

__device__ __forceinline__ uint32_t smem_u32(const void* p) {
    uint32_t a;
    asm("{ .reg .u64 t; cvta.to.shared.u64 t, %1; cvt.u32.u64 %0, t; }" : "=r"(a) : "l"(p));
    return a;
}
__device__ __forceinline__ void ldm_x4(uint32_t* r, uint32_t a) {
    asm volatile("ldmatrix.sync.aligned.m8n8.x4.shared.b16 {%0,%1,%2,%3}, [%4];"
                 : "=r"(r[0]), "=r"(r[1]), "=r"(r[2]), "=r"(r[3]) : "r"(a));
}
__device__ __forceinline__ void mma_bf16(float* c, const uint32_t* a, const uint32_t* b) {
    asm volatile(
        "mma.sync.aligned.m16n8k16.row.col.f32.bf16.bf16.f32 "
        "{%0,%1,%2,%3}, {%4,%5,%6,%7}, {%8,%9}, {%0,%1,%2,%3};"
        : "+f"(c[0]), "+f"(c[1]), "+f"(c[2]), "+f"(c[3])
        : "r"(a[0]), "r"(a[1]), "r"(a[2]), "r"(a[3]), "r"(b[0]), "r"(b[1]));
}
__device__ __forceinline__ void mma_f16(float* c, const uint32_t* a, const uint32_t* b) {
    asm volatile(
        "mma.sync.aligned.m16n8k16.row.col.f32.f16.f16.f32 "
        "{%0,%1,%2,%3}, {%4,%5,%6,%7}, {%8,%9}, {%0,%1,%2,%3};"
        : "+f"(c[0]), "+f"(c[1]), "+f"(c[2]), "+f"(c[3])
        : "r"(a[0]), "r"(a[1]), "r"(a[2]), "r"(a[3]), "r"(b[0]), "r"(b[1]));
}
__device__ __forceinline__ void bf16_split(float v, uint16_t& h, uint16_t& l) {
    __nv_bfloat16 hb = __float2bfloat16(v);
    __nv_bfloat16 lb = __float2bfloat16(v - __bfloat162float(hb));
    h = __bfloat16_as_ushort(hb);
    l = __bfloat16_as_ushort(lb);
}
__device__ __forceinline__ uint32_t prmt_hi(uint32_t a, uint32_t b) {
    uint32_t d;
    asm("prmt.b32 %0, %1, %2, 0x7632;" : "=r"(d) : "r"(a), "r"(b));
    return d;
}
__device__ __forceinline__ void split4(float4 s, uint2& hp, uint2& lp) {
    uint32_t u0 = __float_as_uint(s.x), u1 = __float_as_uint(s.y);
    uint32_t u2 = __float_as_uint(s.z), u3 = __float_as_uint(s.w);
    hp.x = prmt_hi(u0, u1);
    hp.y = prmt_hi(u2, u3);
    float l0 = s.x - __uint_as_float(u0 & 0xFFFF0000u);
    float l1 = s.y - __uint_as_float(u1 & 0xFFFF0000u);
    float l2 = s.z - __uint_as_float(u2 & 0xFFFF0000u);
    float l3 = s.w - __uint_as_float(u3 & 0xFFFF0000u);
    lp.x = prmt_hi(__float_as_uint(l0), __float_as_uint(l1));
    lp.y = prmt_hi(__float_as_uint(l2), __float_as_uint(l3));
}
// pack two floats -> f16x2 (lo arg in low half)
__device__ __forceinline__ uint32_t f16x2(float lo, float hi) {
    uint32_t d;
    asm("cvt.rn.f16x2.f32 %0, %1, %2;" : "=r"(d) : "f"(hi), "f"(lo));
    return d;
}
__device__ __forceinline__ void cp16(uint32_t dst, const void* src) {
    asm volatile("cp.async.cg.shared.global [%0], [%1], 16;" :: "r"(dst), "l"(src));
}
__device__ __forceinline__ void cp_commit() { asm volatile("cp.async.commit_group;" ::: "memory"); }
__device__ __forceinline__ void cp_wait0()  { asm volatile("cp.async.wait_group 0;" ::: "memory"); }
#define BAR_SYNC(id)   asm volatile("bar.sync %0, 512;"   :: "r"(id) : "memory")
#define BAR_ARRIVE(id) asm volatile("bar.arrive %0, 512;" :: "r"(id) : "memory")

// ---------------- x: NCHW -> NHWC ----------------
__global__ void k_tr_x(const float* __restrict__ x) {
    __shared__ float sm[32][33];
    int b = blockIdx.z, ci0 = blockIdx.y * 32, hw0 = blockIdx.x * 32;
    int tx = threadIdx.x, ty = threadIdx.y;
#pragma unroll
    for (int i = 0; i < 4; ++i) {
        int ci = ci0 + ty + i * 8;
        sm[ty + i * 8][tx] = x[(b * CI_ + ci) * HW_ + hw0 + tx];
    }
    __syncthreads();
#pragma unroll
    for (int i = 0; i < 4; ++i) {
        int hw = hw0 + ty + i * 8;
        g_x_nhwc[(b * HW_ + hw) * CI_ + ci0 + tx] = sm[tx][ty + i * 8];
    }
}

// ---------------- prep: BN zero + both weight transforms ----------------
__global__ void k_prep(const float* __restrict__ w_dcn, const float* __restrict__ w_off) {
    int idx = blockIdx.x * 256 + threadIdx.x;
    if (idx < 128) { g_sum[idx] = 0.0; g_sumsq[idx] = 0.0; }
    if (idx < KK_ * CO_ * CI_) {
        int tap = idx >> 14;
        int r   = idx & 16383;
        int co  = r >> 7;
        int ci  = r & 127;
        float w = w_dcn[(co * CI_ + ci) * KK_ + tap];
        uint16_t h, l;
        bf16_split(w, h, l);
        g_wb_hi[idx] = __ushort_as_bfloat16(h);
        g_wb_lo[idx] = __ushort_as_bfloat16(l);
    }
    if (idx < KK_ * 32 * CI_) {
        int tap = idx >> 12;
        int r   = idx & 4095;
        int co  = r >> 7;
        int ci  = r & 127;
        float w = (co < 18) ? w_off[(co * CI_ + ci) * KK_ + tap] : 0.f;
        __half hi = __float2half_rn(w);
        __half lo = __float2half_rn(w - __half2float(hi));
        g_wo_hi[idx] = hi;
        g_wo_lo[idx] = lo;
    }
}

#define RS 272   // padded stride for k_offT

// ---------------- offset conv, tensorized fp16 2-pass (R11, measured faster) --
#define OFF_A   0
#define OFF_BHI 34816
#define OFF_BLO 43520
#define OFF_TOT 52224

__global__ void __launch_bounds__(256, 2) k_offT(const float* __restrict__ b_off) {
    extern __shared__ char sb[];
    uint32_t sbase = smem_u32(sb);
    int tid = threadIdx.x;
    int wid = tid >> 5, lid = tid & 31;
    int px0 = blockIdx.x * 128;

    float acc[4][4];
#pragma unroll
    for (int ni = 0; ni < 4; ++ni)
#pragma unroll
        for (int j = 0; j < 4; ++j) acc[ni][j] = 0.f;

    uint32_t a_lane = (uint32_t)(wid * 16 + (lid & 15)) * RS + ((lid >> 4) << 4);
    uint32_t b_lane4 = (uint32_t)((lid & 7) | ((lid >> 4) << 3)) * RS + (((lid >> 3) & 1) << 4);

    for (int k = 0; k < 9; ++k) {
        int ky = k / 3, kx = k - ky * 3;
        __syncthreads();
#pragma unroll
        for (int t = 0; t < 2; ++t) {
            int e = tid + t * 256;
            int row = e >> 4, c16 = e & 15;
            *(uint4*)(sb + OFF_BHI + row * RS + c16 * 16) =
                *(const uint4*)(g_wo_hi + k * 4096 + row * 128 + c16 * 8);
            *(uint4*)(sb + OFF_BLO + row * RS + c16 * 16) =
                *(const uint4*)(g_wo_lo + k * 4096 + row * 128 + c16 * 8);
        }
#pragma unroll 2
        for (int i = 0; i < 16; ++i) {
            int p = i * 8 + wid;
            int px = px0 + p;
            int b = px >> 14, h = (px >> 7) & 127, w = px & 127;
            int y = h - 1 + ky, xx = w - 1 + kx;
            uint2 hp = make_uint2(0u, 0u);
            if ((unsigned)y < (unsigned)H_ && (unsigned)xx < (unsigned)W_) {
                float4 v = *(const float4*)(g_x_nhwc + ((b * H_ + y) * W_ + xx) * CI_ + lid * 4);
                hp.x = f16x2(v.x, v.y);
                hp.y = f16x2(v.z, v.w);
            }
            *(uint2*)(sb + OFF_A + (uint32_t)p * RS + (uint32_t)lid * 8) = hp;
        }
        __syncthreads();
#pragma unroll
        for (int ks = 0; ks < 8; ++ks) {
            uint32_t kb = (uint32_t)ks * 32;
            uint32_t ah[4], b4[2][4];
            ldm_x4(ah, sbase + OFF_A + a_lane + kb);
#pragma unroll
            for (int ni2 = 0; ni2 < 2; ++ni2)
                ldm_x4(b4[ni2], sbase + OFF_BHI + b_lane4 + (uint32_t)(ni2 * 16) * RS + kb);
#pragma unroll
            for (int ni2 = 0; ni2 < 2; ++ni2)
#pragma unroll
                for (int half = 0; half < 2; ++half)
                    mma_f16(acc[ni2 * 2 + half], ah, b4[ni2] + half * 2);
#pragma unroll
            for (int ni2 = 0; ni2 < 2; ++ni2)
                ldm_x4(b4[ni2], sbase + OFF_BLO + b_lane4 + (uint32_t)(ni2 * 16) * RS + kb);
#pragma unroll
            for (int ni2 = 0; ni2 < 2; ++ni2)
#pragma unroll
                for (int half = 0; half < 2; ++half)
                    mma_f16(acc[ni2 * 2 + half], ah, b4[ni2] + half * 2);
        }
    }
    int rofs = lid >> 2, cofs = (lid & 3) * 2;
    int r0 = px0 + wid * 16 + rofs;
#pragma unroll
    for (int ni = 0; ni < 4; ++ni) {
        int c = ni * 8 + cofs;
        if (c < 18) {
            float2 bo = *(const float2*)(b_off + c);
            *(float2*)(g_off + r0 * 18 + c) =
                make_float2(acc[ni][0] + bo.x, acc[ni][1] + bo.y);
            *(float2*)(g_off + (r0 + 8) * 18 + c) =
                make_float2(acc[ni][2] + bo.x, acc[ni][3] + bo.y);
        }
    }
}

// ---------------- main: R8 exact (warp-specialized bf16 3-pass) ---------------
// smem (XOR-swizzled 256B rows): A stages 2x64KB (hi+lo), Bhi 2x32KB, Blo 1x32KB
// barriers: A_FULL 1,2  A_FREE 3,4  BLO_FULL 5  BLO_FREE 6
#define A_ST(s)   ((uint32_t)(s) * 65536u)
#define A_LOOFF   32768u
#define BHI_ST(s) (131072u + (uint32_t)(s) * 32768u)
#define BLO_ST    196608u
#define WS_TOT    229376
#define RSF       132

struct Samp {
    float4 v00, v01, v10, v11;
    float w00, w01, w10, w11;
    uint32_t off;
};

__device__ __forceinline__ void samp_issueP(Samp& S, int p, int t, int ky, int kx,
                                            int px0, int lid) {
    int px = px0 + p;
    int b = px >> 14, h = (px >> 7) & 127, w = px & 127;
    float2 d = *(const float2*)(g_off + px * 18 + 2 * t);
    float ysf = (float)(h - 1 + ky) + d.x;
    float xsf = (float)(w - 1 + kx) + d.y;
    float fy = floorf(ysf), fx = floorf(xsf);
    float wy = ysf - fy, wx = xsf - fx;
    int iy0 = (int)fy, ix0 = (int)fx;
    int iy1 = iy0 + 1, ix1 = ix0 + 1;
    float my0 = (iy0 >= 0 && iy0 < H_) ? 1.f : 0.f;
    float my1 = (iy1 >= 0 && iy1 < H_) ? 1.f : 0.f;
    float mx0 = (ix0 >= 0 && ix0 < W_) ? 1.f : 0.f;
    float mx1 = (ix1 >= 0 && ix1 < W_) ? 1.f : 0.f;
    int cy0 = min(H_ - 1, max(0, iy0)), cy1 = min(H_ - 1, max(0, iy1));
    int cx0 = min(W_ - 1, max(0, ix0)), cx1 = min(W_ - 1, max(0, ix1));
    int base = b * HW_;
    int c4 = lid * 4;
    S.v00 = *(const float4*)(g_x_nhwc + (base + cy0 * W_ + cx0) * CI_ + c4);
    S.v01 = *(const float4*)(g_x_nhwc + (base + cy0 * W_ + cx1) * CI_ + c4);
    S.v10 = *(const float4*)(g_x_nhwc + (base + cy1 * W_ + cx0) * CI_ + c4);
    S.v11 = *(const float4*)(g_x_nhwc + (base + cy1 * W_ + cx1) * CI_ + c4);
    S.w00 = (1.f - wy) * (1.f - wx) * my0 * mx0;
    S.w01 = (1.f - wy) * wx * my0 * mx1;
    S.w10 = wy * (1.f - wx) * my1 * mx0;
    S.w11 = wy * wx * my1 * mx1;
    S.off = (uint32_t)p * 256u + (((((uint32_t)lid >> 1) ^ ((uint32_t)p & 7u)) << 4) | (((uint32_t)lid & 1u) << 3));
}

__device__ __forceinline__ void samp_storeP(char* sb, uint32_t abase, const Samp& S) {
    float4 s;
    s.x = fmaf(S.v11.x, S.w11, fmaf(S.v10.x, S.w10, fmaf(S.v01.x, S.w01, S.v00.x * S.w00)));
    s.y = fmaf(S.v11.y, S.w11, fmaf(S.v10.y, S.w10, fmaf(S.v01.y, S.w01, S.v00.y * S.w00)));
    s.z = fmaf(S.v11.z, S.w11, fmaf(S.v10.z, S.w10, fmaf(S.v01.z, S.w01, S.v00.z * S.w00)));
    s.w = fmaf(S.v11.w, S.w11, fmaf(S.v10.w, S.w10, fmaf(S.v01.w, S.w01, S.v00.w * S.w00)));
    uint2 hp, lp;
    split4(s, hp, lp);
    *(uint2*)(sb + abase + S.off) = hp;
    *(uint2*)(sb + abase + A_LOOFF + S.off) = lp;
}

__device__ __forceinline__ void copy_B_swz(uint32_t dstbase, const char* src, int ptid) {
#pragma unroll
    for (int j = 0; j < 8; ++j) {
        int c = ptid + j * 256;
        uint32_t row = (uint32_t)(c >> 4), c16 = (uint32_t)(c & 15);
        uint32_t dof = row * 256u + ((c16 ^ (row & 7u)) << 4);
        cp16(dstbase + dof, src + c * 16);
    }
}

__global__ void __launch_bounds__(512, 1) k_mainWS() {
    extern __shared__ char sb[];
    uint32_t sbase = smem_u32(sb);
    int tid = threadIdx.x;
    int wid = tid >> 5, lid = tid & 31;
    int px0 = blockIdx.x * 128;

    float acc[2][8][4];
#pragma unroll
    for (int mi = 0; mi < 2; ++mi)
#pragma unroll
        for (int nf = 0; nf < 8; ++nf)
#pragma unroll
            for (int j = 0; j < 4; ++j) acc[mi][nf][j] = 0.f;

    if (wid < 8) {
        // ================= CONSUMER =================
        int mw = wid >> 1, nw = wid & 1;
        uint32_t rA[2], rA7[2];
#pragma unroll
        for (int mi = 0; mi < 2; ++mi) {
            uint32_t r = (uint32_t)(mw * 32 + mi * 16 + (lid & 15));
            rA[mi] = r * 256u; rA7[mi] = r & 7u;
        }
        uint32_t chAh = (uint32_t)(lid >> 4);
        uint32_t rowp = (uint32_t)((lid & 7) | ((lid >> 4) << 3));
        uint32_t chBh = (uint32_t)((lid >> 3) & 1);
        uint32_t rB[4], rB7[4];
#pragma unroll
        for (int n = 0; n < 4; ++n) {
            uint32_t r = (uint32_t)(nw * 64 + n * 16) + rowp;
            rB[n] = r * 256u; rB7[n] = r & 7u;
        }

        for (int k = 0; k < 9; ++k) {
            BAR_SYNC(1 + (k & 1));     // A[k] + Bhi[k] ready
            BAR_SYNC(5);               // Blo[k] ready
            uint32_t Ast = sbase + A_ST(k & 1);
            uint32_t Bh  = sbase + BHI_ST(k & 1);
            uint32_t Bl  = sbase + BLO_ST;
#pragma unroll
            for (int s = 0; s < 8; ++s) {
                uint32_t cA = (uint32_t)(2 * s) + chAh;
                uint32_t cB = (uint32_t)(2 * s) + chBh;
                uint32_t ah[2][4], bh[4][4], bl[4][4];
#pragma unroll
                for (int mi = 0; mi < 2; ++mi)
                    ldm_x4(ah[mi], Ast + rA[mi] + ((cA ^ rA7[mi]) << 4));
#pragma unroll
                for (int n = 0; n < 4; ++n)
                    ldm_x4(bh[n], Bh + rB[n] + ((cB ^ rB7[n]) << 4));
#pragma unroll
                for (int n = 0; n < 4; ++n)
                    ldm_x4(bl[n], Bl + rB[n] + ((cB ^ rB7[n]) << 4));
                // pass hh
#pragma unroll
                for (int mi = 0; mi < 2; ++mi)
#pragma unroll
                    for (int nf = 0; nf < 8; ++nf)
                        mma_bf16(acc[mi][nf], ah[mi], bh[nf >> 1] + (nf & 1) * 2);
                // pass hl
#pragma unroll
                for (int mi = 0; mi < 2; ++mi)
#pragma unroll
                    for (int nf = 0; nf < 8; ++nf)
                        mma_bf16(acc[mi][nf], ah[mi], bl[nf >> 1] + (nf & 1) * 2);
                // pass lh (al loaded late)
                uint32_t al[2][4];
#pragma unroll
                for (int mi = 0; mi < 2; ++mi)
                    ldm_x4(al[mi], Ast + A_LOOFF + rA[mi] + ((cA ^ rA7[mi]) << 4));
#pragma unroll
                for (int mi = 0; mi < 2; ++mi)
#pragma unroll
                    for (int nf = 0; nf < 8; ++nf)
                        mma_bf16(acc[mi][nf], al[mi], bh[nf >> 1] + (nf & 1) * 2);
            }
            BAR_ARRIVE(6);             // Blo free
            BAR_ARRIVE(3 + (k & 1));   // A stage free
        }
    } else {
        // ================= PRODUCER =================
        int wp = wid - 8;
        int ptid = wp * 32 + lid;
        for (int k = 0; k < 9; ++k) {
            int st = k & 1;
            if (k >= 2) BAR_SYNC(3 + st);
            copy_B_swz(sbase + BHI_ST(st), (const char*)g_wb_hi + k * 32768, ptid);
            cp_commit();
            int ky = k / 3, kx = k - ky * 3;
            uint32_t Ast = A_ST(st);
            Samp S0, S1;
            samp_issueP(S0, wp, k, ky, kx, px0, lid);
#pragma unroll
            for (int i = 0; i < 16; ++i) {
                if ((i & 1) == 0) {
                    if (i < 15) samp_issueP(S1, (i + 1) * 8 + wp, k, ky, kx, px0, lid);
                    samp_storeP(sb, Ast, S0);
                } else {
                    if (i < 15) samp_issueP(S0, (i + 1) * 8 + wp, k, ky, kx, px0, lid);
                    samp_storeP(sb, Ast, S1);
                }
            }
            cp_wait0();
            __threadfence_block();
            BAR_ARRIVE(1 + st);        // A[k] + Bhi[k] full
            if (k >= 1) BAR_SYNC(6);   // Blo buffer free
            copy_B_swz(sbase + BLO_ST, (const char*)g_wb_lo + k * 32768, ptid);
            cp_commit();
            cp_wait0();
            BAR_ARRIVE(5);             // Blo[k] full
        }
    }

    __syncthreads();
    // ---- epilogue: consumers stage acc, all store + BN partials ----
    float* stg = (float*)sb;
    if (wid < 8) {
        int mw = wid >> 1, nw = wid & 1;
        int rofs = lid >> 2, cofs = (lid & 3) * 2;
#pragma unroll
        for (int mi = 0; mi < 2; ++mi) {
            int r0 = mw * 32 + mi * 16 + rofs;
#pragma unroll
            for (int nf = 0; nf < 8; ++nf) {
                int co = nw * 64 + nf * 8 + cofs;
                *(float2*)(stg + r0 * RSF + co)       = make_float2(acc[mi][nf][0], acc[mi][nf][1]);
                *(float2*)(stg + (r0 + 8) * RSF + co) = make_float2(acc[mi][nf][2], acc[mi][nf][3]);
            }
        }
    }
    __syncthreads();
#pragma unroll
    for (int tt = 0; tt < 8; ++tt) {
        int idx = tid + tt * 512;
        int row = idx >> 5, c4 = (idx & 31) * 4;
        float4 v = *(const float4*)(stg + row * RSF + c4);
        *(float4*)(g_out + (px0 + row) * CO_ + c4) = v;
    }
    {
        int co = tid & 127, q = tid >> 7;
        float s = 0.f, qq = 0.f;
#pragma unroll
        for (int r = 0; r < 32; ++r) {
            float v = stg[(q * 32 + r) * RSF + co];
            s += v; qq = fmaf(v, v, qq);
        }
        float* reds = (float*)(sb + BHI_ST(0));
        float* redq = reds + 512;
        reds[q * 128 + co] = s;
        redq[q * 128 + co] = qq;
        __syncthreads();
        if (tid < 128) {
            float ss = reds[tid] + reds[128 + tid] + reds[256 + tid] + reds[384 + tid];
            float sq = redq[tid] + redq[128 + tid] + redq[256 + tid] + redq[384 + tid];
            atomicAdd(&g_sum[tid], (double)ss);
            atomicAdd(&g_sumsq[tid], (double)sq);
        }
    }
}

// ---------------- BN finalize ----------------
__global__ void k_fin(const float* __restrict__ gamma, const float* __restrict__ beta) {
    int c = threadIdx.x;
    if (c < CO_) {
        double N = (double)NPIX;
        double mean = g_sum[c] / N;
        double var  = g_sumsq[c] / N - mean * mean;
        float a = gamma[c] * rsqrtf((float)var + BN_EPS);
        g_scale[c] = a;
        g_shift[c] = beta[c] - (float)mean * a;
    }
}

// ---------------- apply BN + ReLU + transpose [px][co] -> NCHW ----------------
__global__ void k_apply(float* __restrict__ out) {
    __shared__ float sm[32][33];
    int b = blockIdx.z, co0 = blockIdx.y * 32, hw0 = blockIdx.x * 32;
    int tx = threadIdx.x, ty = threadIdx.y;
#pragma unroll
    for (int i = 0; i < 4; ++i) {
        int hw = hw0 + ty + i * 8;
        sm[ty + i * 8][tx] = g_out[(b * HW_ + hw) * CO_ + co0 + tx];
    }
    __syncthreads();
#pragma unroll
    for (int i = 0; i < 4; ++i) {
        int co = co0 + ty + i * 8;
        float a = g_scale[co], sh = g_shift[co];
        float v = fmaf(sm[tx][ty + i * 8], a, sh);
        out[(b * CO_ + co) * HW_ + hw0 + tx] = fmaxf(v, 0.f);
    }
}

// ---------------- launch ----------------
extern "C" void kernel_launch(void* const* d_in, const int* in_sizes, int n_in,
                              void* d_out, int out_size) {
    const float* x      = (const float*)d_in[0];
    const float* w_off  = (const float*)d_in[1];
    const float* b_off  = (const float*)d_in[2];
    const float* w_dcn  = (const float*)d_in[3];
    const float* gamma  = (const float*)d_in[4];
    const float* beta   = (const float*)d_in[5];
    float* out = (float*)d_out;

    cudaFuncSetAttribute(k_offT,   cudaFuncAttributeMaxDynamicSharedMemorySize, OFF_TOT);
    cudaFuncSetAttribute(k_mainWS, cudaFuncAttributeMaxDynamicSharedMemorySize, WS_TOT);

    dim3 tb(32, 8);
    k_tr_x<<<dim3(512, 4, B_), tb>>>(x);          // launch 0
    k_prep<<<576, 256>>>(w_dcn, w_off);           // launch 1
    k_offT<<<512, 256, OFF_TOT>>>(b_off);         // launch 2
    k_mainWS<<<512, 512, WS_TOT>>>();             // launch 3  <- ncu capture slot
    k_fin<<<1, 128>>>(gamma, beta);               // launch 4
    k_apply<<<dim3(512, 4, B_), tb>>>(out);       // launch 5
}

// round 13
// speedup vs baseline: 1.5891x; 1.1022x over previous
#include <cuda_runtime.h>
#include <cuda_bf16.h>
#include <cuda_fp16.h>
#include <cstdint>

#define B_   4
#define CI_  128
#define CO_  128
#define H_   128
#define W_   128
#define HW_  (H_*W_)
#define KK_  9
#define NPIX (B_*HW_)   // 65536
#define BN_EPS 0.001f

// ---------------- scratch ----------------
__device__ float  g_x_nhwc[NPIX*CI_];                       // [b][h][w][ci] fp32 (offT)
__device__ __align__(16) __half g_x_h[NPIX*CI_];            // same, fp16 (main gathers)
__device__ float  g_off[NPIX*18];                           // [px][18]
__device__ __align__(16) __half g_wb_hi[KK_*CO_*CI_];       // main w fp16 hi
__device__ __align__(16) __half g_wb_lo[KK_*CO_*CI_];       // main w fp16 lo
__device__ __align__(16) __half g_wo_hi[KK_*32*CI_];        // offT w fp16 hi
__device__ __align__(16) __half g_wo_lo[KK_*32*CI_];        // offT w fp16 lo
__device__ float  g_out[NPIX*CO_];                          // [px][co]
__device__ double g_sum[CO_];
__device__ double g_sumsq[CO_];
__device__ float  g_scale[CO_];
__device__ float  g_shift[CO_];

__device__ __forceinline__ uint32_t smem_u32(const void* p) {
    uint32_t a;
    asm("{ .reg .u64 t; cvta.to.shared.u64 t, %1; cvt.u32.u64 %0, t; }" : "=r"(a) : "l"(p));
    return a;
}
__device__ __forceinline__ void ldm_x4(uint32_t* r, uint32_t a) {
    asm volatile("ldmatrix.sync.aligned.m8n8.x4.shared.b16 {%0,%1,%2,%3}, [%4];"
                 : "=r"(r[0]), "=r"(r[1]), "=r"(r[2]), "=r"(r[3]) : "r"(a));
}
__device__ __forceinline__ void mma_f16(float* c, const uint32_t* a, const uint32_t* b) {
    asm volatile(
        "mma.sync.aligned.m16n8k16.row.col.f32.f16.f16.f32 "
        "{%0,%1,%2,%3}, {%4,%5,%6,%7}, {%8,%9}, {%0,%1,%2,%3};"
        : "+f"(c[0]), "+f"(c[1]), "+f"(c[2]), "+f"(c[3])
        : "r"(a[0]), "r"(a[1]), "r"(a[2]), "r"(a[3]), "r"(b[0]), "r"(b[1]));
}
// pack two floats -> f16x2 (first arg in low half)
__device__ __forceinline__ uint32_t f16x2(float lo, float hi) {
    uint32_t d;
    asm("cvt.rn.f16x2.f32 %0, %1, %2;" : "=r"(d) : "f"(hi), "f"(lo));
    return d;
}
__device__ __forceinline__ void cp16(uint32_t dst, const void* src) {
    asm volatile("cp.async.cg.shared.global [%0], [%1], 16;" :: "r"(dst), "l"(src));
}
__device__ __forceinline__ void cp_commit() { asm volatile("cp.async.commit_group;" ::: "memory"); }
__device__ __forceinline__ void cp_wait0()  { asm volatile("cp.async.wait_group 0;" ::: "memory"); }
#define BAR_SYNC(id)   asm volatile("bar.sync %0, 512;"   :: "r"(id) : "memory")
#define BAR_ARRIVE(id) asm volatile("bar.arrive %0, 512;" :: "r"(id) : "memory")

// ---------------- x: NCHW -> NHWC (fp32 + fp16 copies) ----------------
__global__ void k_tr_x(const float* __restrict__ x) {
    __shared__ float sm[32][33];
    int b = blockIdx.z, ci0 = blockIdx.y * 32, hw0 = blockIdx.x * 32;
    int tx = threadIdx.x, ty = threadIdx.y;
#pragma unroll
    for (int i = 0; i < 4; ++i) {
        int ci = ci0 + ty + i * 8;
        sm[ty + i * 8][tx] = x[(b * CI_ + ci) * HW_ + hw0 + tx];
    }
    __syncthreads();
#pragma unroll
    for (int i = 0; i < 4; ++i) {
        int hw = hw0 + ty + i * 8;
        float v = sm[tx][ty + i * 8];
        int o = (b * HW_ + hw) * CI_ + ci0 + tx;
        g_x_nhwc[o] = v;
        g_x_h[o] = __float2half_rn(v);
    }
}

// ---------------- prep: BN zero + both weight transforms (fp16 hi/lo) ---------
__global__ void k_prep(const float* __restrict__ w_dcn, const float* __restrict__ w_off) {
    int idx = blockIdx.x * 256 + threadIdx.x;
    if (idx < 128) { g_sum[idx] = 0.0; g_sumsq[idx] = 0.0; }
    if (idx < KK_ * CO_ * CI_) {
        int tap = idx >> 14;
        int r   = idx & 16383;
        int co  = r >> 7;
        int ci  = r & 127;
        float w = w_dcn[(co * CI_ + ci) * KK_ + tap];
        __half hi = __float2half_rn(w);
        __half lo = __float2half_rn(w - __half2float(hi));
        g_wb_hi[idx] = hi;
        g_wb_lo[idx] = lo;
    }
    if (idx < KK_ * 32 * CI_) {
        int tap = idx >> 12;
        int r   = idx & 4095;
        int co  = r >> 7;
        int ci  = r & 127;
        float w = (co < 18) ? w_off[(co * CI_ + ci) * KK_ + tap] : 0.f;
        __half hi = __float2half_rn(w);
        __half lo = __float2half_rn(w - __half2float(hi));
        g_wo_hi[idx] = hi;
        g_wo_lo[idx] = lo;
    }
}

#define RS 272   // padded stride for k_offT

// ---------------- offset conv, tensorized fp16 2-pass (unchanged, fp32 x) -----
#define OFF_A   0
#define OFF_BHI 34816
#define OFF_BLO 43520
#define OFF_TOT 52224

__global__ void __launch_bounds__(256, 2) k_offT(const float* __restrict__ b_off) {
    extern __shared__ char sb[];
    uint32_t sbase = smem_u32(sb);
    int tid = threadIdx.x;
    int wid = tid >> 5, lid = tid & 31;
    int px0 = blockIdx.x * 128;

    float acc[4][4];
#pragma unroll
    for (int ni = 0; ni < 4; ++ni)
#pragma unroll
        for (int j = 0; j < 4; ++j) acc[ni][j] = 0.f;

    uint32_t a_lane = (uint32_t)(wid * 16 + (lid & 15)) * RS + ((lid >> 4) << 4);
    uint32_t b_lane4 = (uint32_t)((lid & 7) | ((lid >> 4) << 3)) * RS + (((lid >> 3) & 1) << 4);

    for (int k = 0; k < 9; ++k) {
        int ky = k / 3, kx = k - ky * 3;
        __syncthreads();
#pragma unroll
        for (int t = 0; t < 2; ++t) {
            int e = tid + t * 256;
            int row = e >> 4, c16 = e & 15;
            *(uint4*)(sb + OFF_BHI + row * RS + c16 * 16) =
                *(const uint4*)(g_wo_hi + k * 4096 + row * 128 + c16 * 8);
            *(uint4*)(sb + OFF_BLO + row * RS + c16 * 16) =
                *(const uint4*)(g_wo_lo + k * 4096 + row * 128 + c16 * 8);
        }
#pragma unroll 2
        for (int i = 0; i < 16; ++i) {
            int p = i * 8 + wid;
            int px = px0 + p;
            int b = px >> 14, h = (px >> 7) & 127, w = px & 127;
            int y = h - 1 + ky, xx = w - 1 + kx;
            uint2 hp = make_uint2(0u, 0u);
            if ((unsigned)y < (unsigned)H_ && (unsigned)xx < (unsigned)W_) {
                float4 v = *(const float4*)(g_x_nhwc + ((b * H_ + y) * W_ + xx) * CI_ + lid * 4);
                hp.x = f16x2(v.x, v.y);
                hp.y = f16x2(v.z, v.w);
            }
            *(uint2*)(sb + OFF_A + (uint32_t)p * RS + (uint32_t)lid * 8) = hp;
        }
        __syncthreads();
#pragma unroll
        for (int ks = 0; ks < 8; ++ks) {
            uint32_t kb = (uint32_t)ks * 32;
            uint32_t ah[4], b4[2][4];
            ldm_x4(ah, sbase + OFF_A + a_lane + kb);
#pragma unroll
            for (int ni2 = 0; ni2 < 2; ++ni2)
                ldm_x4(b4[ni2], sbase + OFF_BHI + b_lane4 + (uint32_t)(ni2 * 16) * RS + kb);
#pragma unroll
            for (int ni2 = 0; ni2 < 2; ++ni2)
#pragma unroll
                for (int half = 0; half < 2; ++half)
                    mma_f16(acc[ni2 * 2 + half], ah, b4[ni2] + half * 2);
#pragma unroll
            for (int ni2 = 0; ni2 < 2; ++ni2)
                ldm_x4(b4[ni2], sbase + OFF_BLO + b_lane4 + (uint32_t)(ni2 * 16) * RS + kb);
#pragma unroll
            for (int ni2 = 0; ni2 < 2; ++ni2)
#pragma unroll
                for (int half = 0; half < 2; ++half)
                    mma_f16(acc[ni2 * 2 + half], ah, b4[ni2] + half * 2);
        }
    }
    int rofs = lid >> 2, cofs = (lid & 3) * 2;
    int r0 = px0 + wid * 16 + rofs;
#pragma unroll
    for (int ni = 0; ni < 4; ++ni) {
        int c = ni * 8 + cofs;
        if (c < 18) {
            float2 bo = *(const float2*)(b_off + c);
            *(float2*)(g_off + r0 * 18 + c) =
                make_float2(acc[ni][0] + bo.x, acc[ni][1] + bo.y);
            *(float2*)(g_off + (r0 + 8) * 18 + c) =
                make_float2(acc[ni][2] + bo.x, acc[ni][3] + bo.y);
        }
    }
}

// ---------------- main: R8 skeleton, fp16 A-single x (Bh+Bl) 2-pass -----------
// smem (XOR-swizzled 256B rows): A 2x32KB, Bhi 2x32KB @65536, Blo 1x32KB @131072
// barriers: A_FULL 1,2  A_FREE 3,4  BLO_FULL 5  BLO_FREE 6
#define A_ST(s)   ((uint32_t)(s) * 32768u)
#define BHI_ST(s) (65536u + (uint32_t)(s) * 32768u)
#define BLO_ST    131072u
#define WS_TOT    163840
#define RSF       132

struct Samp {
    uint2 r00, r01, r10, r11;    // fp16x4 per corner
    float w00, w01, w10, w11;
    uint32_t off;
};

__device__ __forceinline__ void samp_issueP(Samp& S, int p, int t, int ky, int kx,
                                            int px0, int lid) {
    int px = px0 + p;
    int b = px >> 14, h = (px >> 7) & 127, w = px & 127;
    float2 d = *(const float2*)(g_off + px * 18 + 2 * t);
    float ysf = (float)(h - 1 + ky) + d.x;
    float xsf = (float)(w - 1 + kx) + d.y;
    float fy = floorf(ysf), fx = floorf(xsf);
    float wy = ysf - fy, wx = xsf - fx;
    int iy0 = (int)fy, ix0 = (int)fx;
    int iy1 = iy0 + 1, ix1 = ix0 + 1;
    float my0 = (iy0 >= 0 && iy0 < H_) ? 1.f : 0.f;
    float my1 = (iy1 >= 0 && iy1 < H_) ? 1.f : 0.f;
    float mx0 = (ix0 >= 0 && ix0 < W_) ? 1.f : 0.f;
    float mx1 = (ix1 >= 0 && ix1 < W_) ? 1.f : 0.f;
    int cy0 = min(H_ - 1, max(0, iy0)), cy1 = min(H_ - 1, max(0, iy1));
    int cx0 = min(W_ - 1, max(0, ix0)), cx1 = min(W_ - 1, max(0, ix1));
    int base = b * HW_;
    int c4 = lid * 4;
    S.r00 = *(const uint2*)(g_x_h + (base + cy0 * W_ + cx0) * CI_ + c4);
    S.r01 = *(const uint2*)(g_x_h + (base + cy0 * W_ + cx1) * CI_ + c4);
    S.r10 = *(const uint2*)(g_x_h + (base + cy1 * W_ + cx0) * CI_ + c4);
    S.r11 = *(const uint2*)(g_x_h + (base + cy1 * W_ + cx1) * CI_ + c4);
    S.w00 = (1.f - wy) * (1.f - wx) * my0 * mx0;
    S.w01 = (1.f - wy) * wx * my0 * mx1;
    S.w10 = wy * (1.f - wx) * my1 * mx0;
    S.w11 = wy * wx * my1 * mx1;
    S.off = (uint32_t)p * 256u + (((((uint32_t)lid >> 1) ^ ((uint32_t)p & 7u)) << 4) | (((uint32_t)lid & 1u) << 3));
}

__device__ __forceinline__ void samp_storeP(char* sb, uint32_t abase, const Samp& S) {
    float2 a0 = __half22float2(*(const __half2*)&S.r00.x);
    float2 a1 = __half22float2(*(const __half2*)&S.r00.y);
    float2 b0 = __half22float2(*(const __half2*)&S.r01.x);
    float2 b1 = __half22float2(*(const __half2*)&S.r01.y);
    float2 c0 = __half22float2(*(const __half2*)&S.r10.x);
    float2 c1 = __half22float2(*(const __half2*)&S.r10.y);
    float2 d0 = __half22float2(*(const __half2*)&S.r11.x);
    float2 d1 = __half22float2(*(const __half2*)&S.r11.y);
    float4 s;
    s.x = fmaf(d0.x, S.w11, fmaf(c0.x, S.w10, fmaf(b0.x, S.w01, a0.x * S.w00)));
    s.y = fmaf(d0.y, S.w11, fmaf(c0.y, S.w10, fmaf(b0.y, S.w01, a0.y * S.w00)));
    s.z = fmaf(d1.x, S.w11, fmaf(c1.x, S.w10, fmaf(b1.x, S.w01, a1.x * S.w00)));
    s.w = fmaf(d1.y, S.w11, fmaf(c1.y, S.w10, fmaf(b1.y, S.w01, a1.y * S.w00)));
    uint2 hp;
    hp.x = f16x2(s.x, s.y);
    hp.y = f16x2(s.z, s.w);
    *(uint2*)(sb + abase + S.off) = hp;
}

__device__ __forceinline__ void copy_B_swz(uint32_t dstbase, const char* src, int ptid) {
#pragma unroll
    for (int j = 0; j < 8; ++j) {
        int c = ptid + j * 256;
        uint32_t row = (uint32_t)(c >> 4), c16 = (uint32_t)(c & 15);
        uint32_t dof = row * 256u + ((c16 ^ (row & 7u)) << 4);
        cp16(dstbase + dof, src + c * 16);
    }
}

__global__ void __launch_bounds__(512, 1) k_mainWS() {
    extern __shared__ char sb[];
    uint32_t sbase = smem_u32(sb);
    int tid = threadIdx.x;
    int wid = tid >> 5, lid = tid & 31;
    int px0 = blockIdx.x * 128;

    float acc[2][8][4];
#pragma unroll
    for (int mi = 0; mi < 2; ++mi)
#pragma unroll
        for (int nf = 0; nf < 8; ++nf)
#pragma unroll
            for (int j = 0; j < 4; ++j) acc[mi][nf][j] = 0.f;

    if (wid < 8) {
        // ================= CONSUMER =================
        int mw = wid >> 1, nw = wid & 1;
        uint32_t rA[2], rA7[2];
#pragma unroll
        for (int mi = 0; mi < 2; ++mi) {
            uint32_t r = (uint32_t)(mw * 32 + mi * 16 + (lid & 15));
            rA[mi] = r * 256u; rA7[mi] = r & 7u;
        }
        uint32_t chAh = (uint32_t)(lid >> 4);
        uint32_t rowp = (uint32_t)((lid & 7) | ((lid >> 4) << 3));
        uint32_t chBh = (uint32_t)((lid >> 3) & 1);
        uint32_t rB[4], rB7[4];
#pragma unroll
        for (int n = 0; n < 4; ++n) {
            uint32_t r = (uint32_t)(nw * 64 + n * 16) + rowp;
            rB[n] = r * 256u; rB7[n] = r & 7u;
        }

        for (int k = 0; k < 9; ++k) {
            BAR_SYNC(1 + (k & 1));     // A[k] + Bhi[k] ready
            BAR_SYNC(5);               // Blo[k] ready
            uint32_t Ast = sbase + A_ST(k & 1);
            uint32_t Bh  = sbase + BHI_ST(k & 1);
            uint32_t Bl  = sbase + BLO_ST;
#pragma unroll
            for (int s = 0; s < 8; ++s) {
                uint32_t cA = (uint32_t)(2 * s) + chAh;
                uint32_t cB = (uint32_t)(2 * s) + chBh;
                uint32_t ah[2][4], bh[4][4], bl[4][4];
#pragma unroll
                for (int mi = 0; mi < 2; ++mi)
                    ldm_x4(ah[mi], Ast + rA[mi] + ((cA ^ rA7[mi]) << 4));
#pragma unroll
                for (int n = 0; n < 4; ++n)
                    ldm_x4(bh[n], Bh + rB[n] + ((cB ^ rB7[n]) << 4));
#pragma unroll
                for (int n = 0; n < 4; ++n)
                    ldm_x4(bl[n], Bl + rB[n] + ((cB ^ rB7[n]) << 4));
                // pass A*Bh
#pragma unroll
                for (int mi = 0; mi < 2; ++mi)
#pragma unroll
                    for (int nf = 0; nf < 8; ++nf)
                        mma_f16(acc[mi][nf], ah[mi], bh[nf >> 1] + (nf & 1) * 2);
                // pass A*Bl
#pragma unroll
                for (int mi = 0; mi < 2; ++mi)
#pragma unroll
                    for (int nf = 0; nf < 8; ++nf)
                        mma_f16(acc[mi][nf], ah[mi], bl[nf >> 1] + (nf & 1) * 2);
            }
            BAR_ARRIVE(6);             // Blo free
            BAR_ARRIVE(3 + (k & 1));   // A stage free
        }
    } else {
        // ================= PRODUCER (R8 structure, fp16 gathers) =================
        int wp = wid - 8;
        int ptid = wp * 32 + lid;
        for (int k = 0; k < 9; ++k) {
            int st = k & 1;
            if (k >= 2) BAR_SYNC(3 + st);
            copy_B_swz(sbase + BHI_ST(st), (const char*)g_wb_hi + k * 32768, ptid);
            cp_commit();
            int ky = k / 3, kx = k - ky * 3;
            uint32_t Ast = A_ST(st);
            Samp S0, S1;
            samp_issueP(S0, wp, k, ky, kx, px0, lid);
#pragma unroll
            for (int i = 0; i < 16; ++i) {
                if ((i & 1) == 0) {
                    if (i < 15) samp_issueP(S1, (i + 1) * 8 + wp, k, ky, kx, px0, lid);
                    samp_storeP(sb, Ast, S0);
                } else {
                    if (i < 15) samp_issueP(S0, (i + 1) * 8 + wp, k, ky, kx, px0, lid);
                    samp_storeP(sb, Ast, S1);
                }
            }
            cp_wait0();
            __threadfence_block();
            BAR_ARRIVE(1 + st);        // A[k] + Bhi[k] full
            if (k >= 1) BAR_SYNC(6);   // Blo buffer free
            copy_B_swz(sbase + BLO_ST, (const char*)g_wb_lo + k * 32768, ptid);
            cp_commit();
            cp_wait0();
            BAR_ARRIVE(5);             // Blo[k] full
        }
    }

    __syncthreads();
    // ---- epilogue: consumers stage acc (A+Bhi regions dead), store + BN ----
    float* stg = (float*)sb;
    if (wid < 8) {
        int mw = wid >> 1, nw = wid & 1;
        int rofs = lid >> 2, cofs = (lid & 3) * 2;
#pragma unroll
        for (int mi = 0; mi < 2; ++mi) {
            int r0 = mw * 32 + mi * 16 + rofs;
#pragma unroll
            for (int nf = 0; nf < 8; ++nf) {
                int co = nw * 64 + nf * 8 + cofs;
                *(float2*)(stg + r0 * RSF + co)       = make_float2(acc[mi][nf][0], acc[mi][nf][1]);
                *(float2*)(stg + (r0 + 8) * RSF + co) = make_float2(acc[mi][nf][2], acc[mi][nf][3]);
            }
        }
    }
    __syncthreads();
#pragma unroll
    for (int tt = 0; tt < 8; ++tt) {
        int idx = tid + tt * 512;
        int row = idx >> 5, c4 = (idx & 31) * 4;
        float4 v = *(const float4*)(stg + row * RSF + c4);
        *(float4*)(g_out + (px0 + row) * CO_ + c4) = v;
    }
    {
        int co = tid & 127, q = tid >> 7;
        float s = 0.f, qq = 0.f;
#pragma unroll
        for (int r = 0; r < 32; ++r) {
            float v = stg[(q * 32 + r) * RSF + co];
            s += v; qq = fmaf(v, v, qq);
        }
        float* reds = (float*)(sb + BLO_ST);
        float* redq = reds + 512;
        reds[q * 128 + co] = s;
        redq[q * 128 + co] = qq;
        __syncthreads();
        if (tid < 128) {
            float ss = reds[tid] + reds[128 + tid] + reds[256 + tid] + reds[384 + tid];
            float sq = redq[tid] + redq[128 + tid] + redq[256 + tid] + redq[384 + tid];
            atomicAdd(&g_sum[tid], (double)ss);
            atomicAdd(&g_sumsq[tid], (double)sq);
        }
    }
}

// ---------------- BN finalize ----------------
__global__ void k_fin(const float* __restrict__ gamma, const float* __restrict__ beta) {
    int c = threadIdx.x;
    if (c < CO_) {
        double N = (double)NPIX;
        double mean = g_sum[c] / N;
        double var  = g_sumsq[c] / N - mean * mean;
        float a = gamma[c] * rsqrtf((float)var + BN_EPS);
        g_scale[c] = a;
        g_shift[c] = beta[c] - (float)mean * a;
    }
}

// ---------------- apply BN + ReLU + transpose [px][co] -> NCHW ----------------
__global__ void k_apply(float* __restrict__ out) {
    __shared__ float sm[32][33];
    int b = blockIdx.z, co0 = blockIdx.y * 32, hw0 = blockIdx.x * 32;
    int tx = threadIdx.x, ty = threadIdx.y;
#pragma unroll
    for (int i = 0; i < 4; ++i) {
        int hw = hw0 + ty + i * 8;
        sm[ty + i * 8][tx] = g_out[(b * HW_ + hw) * CO_ + co0 + tx];
    }
    __syncthreads();
#pragma unroll
    for (int i = 0; i < 4; ++i) {
        int co = co0 + ty + i * 8;
        float a = g_scale[co], sh = g_shift[co];
        float v = fmaf(sm[tx][ty + i * 8], a, sh);
        out[(b * CO_ + co) * HW_ + hw0 + tx] = fmaxf(v, 0.f);
    }
}

// ---------------- launch ----------------
extern "C" void kernel_launch(void* const* d_in, const int* in_sizes, int n_in,
                              void* d_out, int out_size) {
    const float* x      = (const float*)d_in[0];
    const float* w_off  = (const float*)d_in[1];
    const float* b_off  = (const float*)d_in[2];
    const float* w_dcn  = (const float*)d_in[3];
    const float* gamma  = (const float*)d_in[4];
    const float* beta   = (const float*)d_in[5];
    float* out = (float*)d_out;

    cudaFuncSetAttribute(k_offT,   cudaFuncAttributeMaxDynamicSharedMemorySize, OFF_TOT);
    cudaFuncSetAttribute(k_mainWS, cudaFuncAttributeMaxDynamicSharedMemorySize, WS_TOT);

    dim3 tb(32, 8);
    k_tr_x<<<dim3(512, 4, B_), tb>>>(x);          // launch 0
    k_prep<<<576, 256>>>(w_dcn, w_off);           // launch 1
    k_offT<<<512, 256, OFF_TOT>>>(b_off);         // launch 2
    k_mainWS<<<512, 512, WS_TOT>>>();             // launch 3  <- ncu capture slot
    k_fin<<<1, 128>>>(gamma, beta);               // launch 4
    k_apply<<<dim3(512, 4, B_), tb>>>(out);       // launch 5
}

// round 14
// speedup vs baseline: 1.7658x; 1.1112x over previous
#include <cuda_runtime.h>
#include <cuda_fp16.h>
#include <cstdint>

#define B_   4
#define CI_  128
#define CO_  128
#define H_   128
#define W_   128
#define HW_  (H_*W_)
#define KK_  9
#define NPIX (B_*HW_)   // 65536
#define BN_EPS 0.001f

// ---------------- scratch ----------------
__device__ float  g_x_nhwc[NPIX*CI_];                       // [b][h][w][ci] fp32 (offT)
__device__ __align__(16) __half g_x_h[NPIX*CI_];            // same, fp16 (main gathers)
__device__ float  g_off[NPIX*18];                           // [px][18]
__device__ __align__(16) __half g_wb[KK_*CO_*CI_];          // main w fp16
__device__ __align__(16) __half g_wo_hi[KK_*32*CI_];        // offT w fp16 hi
__device__ __align__(16) __half g_wo_lo[KK_*32*CI_];        // offT w fp16 lo
__device__ float  g_out[NPIX*CO_];                          // [px][co]
__device__ double g_sum[CO_];
__device__ double g_sumsq[CO_];
__device__ float  g_scale[CO_];
__device__ float  g_shift[CO_];

__device__ __forceinline__ uint32_t smem_u32(const void* p) {
    uint32_t a;
    asm("{ .reg .u64 t; cvta.to.shared.u64 t, %1; cvt.u32.u64 %0, t; }" : "=r"(a) : "l"(p));
    return a;
}
__device__ __forceinline__ void ldm_x4(uint32_t* r, uint32_t a) {
    asm volatile("ldmatrix.sync.aligned.m8n8.x4.shared.b16 {%0,%1,%2,%3}, [%4];"
                 : "=r"(r[0]), "=r"(r[1]), "=r"(r[2]), "=r"(r[3]) : "r"(a));
}
__device__ __forceinline__ void mma_f16(float* c, const uint32_t* a, const uint32_t* b) {
    asm volatile(
        "mma.sync.aligned.m16n8k16.row.col.f32.f16.f16.f32 "
        "{%0,%1,%2,%3}, {%4,%5,%6,%7}, {%8,%9}, {%0,%1,%2,%3};"
        : "+f"(c[0]), "+f"(c[1]), "+f"(c[2]), "+f"(c[3])
        : "r"(a[0]), "r"(a[1]), "r"(a[2]), "r"(a[3]), "r"(b[0]), "r"(b[1]));
}
// pack two floats -> f16x2 (first arg in low half)
__device__ __forceinline__ uint32_t f16x2(float lo, float hi) {
    uint32_t d;
    asm("cvt.rn.f16x2.f32 %0, %1, %2;" : "=r"(d) : "f"(hi), "f"(lo));
    return d;
}
__device__ __forceinline__ void cp16(uint32_t dst, const void* src) {
    asm volatile("cp.async.cg.shared.global [%0], [%1], 16;" :: "r"(dst), "l"(src));
}
__device__ __forceinline__ void cp_commit() { asm volatile("cp.async.commit_group;" ::: "memory"); }
__device__ __forceinline__ void cp_wait0()  { asm volatile("cp.async.wait_group 0;" ::: "memory"); }
#define BAR_SYNC(id)   asm volatile("bar.sync %0, 512;"   :: "r"(id) : "memory")
#define BAR_ARRIVE(id) asm volatile("bar.arrive %0, 512;" :: "r"(id) : "memory")

// ---------------- x: NCHW -> NHWC (fp32 + fp16 copies) ----------------
__global__ void k_tr_x(const float* __restrict__ x) {
    __shared__ float sm[32][33];
    int b = blockIdx.z, ci0 = blockIdx.y * 32, hw0 = blockIdx.x * 32;
    int tx = threadIdx.x, ty = threadIdx.y;
#pragma unroll
    for (int i = 0; i < 4; ++i) {
        int ci = ci0 + ty + i * 8;
        sm[ty + i * 8][tx] = x[(b * CI_ + ci) * HW_ + hw0 + tx];
    }
    __syncthreads();
#pragma unroll
    for (int i = 0; i < 4; ++i) {
        int hw = hw0 + ty + i * 8;
        float v = sm[tx][ty + i * 8];
        int o = (b * HW_ + hw) * CI_ + ci0 + tx;
        g_x_nhwc[o] = v;
        g_x_h[o] = __float2half_rn(v);
    }
}

// ---------------- prep: BN zero + weight transforms ----------------
__global__ void k_prep(const float* __restrict__ w_dcn, const float* __restrict__ w_off) {
    int idx = blockIdx.x * 256 + threadIdx.x;
    if (idx < 128) { g_sum[idx] = 0.0; g_sumsq[idx] = 0.0; }
    if (idx < KK_ * CO_ * CI_) {
        int tap = idx >> 14;
        int r   = idx & 16383;
        int co  = r >> 7;
        int ci  = r & 127;
        float w = w_dcn[(co * CI_ + ci) * KK_ + tap];
        g_wb[idx] = __float2half_rn(w);
    }
    if (idx < KK_ * 32 * CI_) {
        int tap = idx >> 12;
        int r   = idx & 4095;
        int co  = r >> 7;
        int ci  = r & 127;
        float w = (co < 18) ? w_off[(co * CI_ + ci) * KK_ + tap] : 0.f;
        __half hi = __float2half_rn(w);
        __half lo = __float2half_rn(w - __half2float(hi));
        g_wo_hi[idx] = hi;
        g_wo_lo[idx] = lo;
    }
}

#define RS 272   // padded stride for k_offT

// ---------------- offset conv, tensorized fp16 2-pass (unchanged) -------------
#define OFF_A   0
#define OFF_BHI 34816
#define OFF_BLO 43520
#define OFF_TOT 52224

__global__ void __launch_bounds__(256, 2) k_offT(const float* __restrict__ b_off) {
    extern __shared__ char sb[];
    uint32_t sbase = smem_u32(sb);
    int tid = threadIdx.x;
    int wid = tid >> 5, lid = tid & 31;
    int px0 = blockIdx.x * 128;

    float acc[4][4];
#pragma unroll
    for (int ni = 0; ni < 4; ++ni)
#pragma unroll
        for (int j = 0; j < 4; ++j) acc[ni][j] = 0.f;

    uint32_t a_lane = (uint32_t)(wid * 16 + (lid & 15)) * RS + ((lid >> 4) << 4);
    uint32_t b_lane4 = (uint32_t)((lid & 7) | ((lid >> 4) << 3)) * RS + (((lid >> 3) & 1) << 4);

    for (int k = 0; k < 9; ++k) {
        int ky = k / 3, kx = k - ky * 3;
        __syncthreads();
#pragma unroll
        for (int t = 0; t < 2; ++t) {
            int e = tid + t * 256;
            int row = e >> 4, c16 = e & 15;
            *(uint4*)(sb + OFF_BHI + row * RS + c16 * 16) =
                *(const uint4*)(g_wo_hi + k * 4096 + row * 128 + c16 * 8);
            *(uint4*)(sb + OFF_BLO + row * RS + c16 * 16) =
                *(const uint4*)(g_wo_lo + k * 4096 + row * 128 + c16 * 8);
        }
#pragma unroll 2
        for (int i = 0; i < 16; ++i) {
            int p = i * 8 + wid;
            int px = px0 + p;
            int b = px >> 14, h = (px >> 7) & 127, w = px & 127;
            int y = h - 1 + ky, xx = w - 1 + kx;
            uint2 hp = make_uint2(0u, 0u);
            if ((unsigned)y < (unsigned)H_ && (unsigned)xx < (unsigned)W_) {
                float4 v = *(const float4*)(g_x_nhwc + ((b * H_ + y) * W_ + xx) * CI_ + lid * 4);
                hp.x = f16x2(v.x, v.y);
                hp.y = f16x2(v.z, v.w);
            }
            *(uint2*)(sb + OFF_A + (uint32_t)p * RS + (uint32_t)lid * 8) = hp;
        }
        __syncthreads();
#pragma unroll
        for (int ks = 0; ks < 8; ++ks) {
            uint32_t kb = (uint32_t)ks * 32;
            uint32_t ah[4], b4[2][4];
            ldm_x4(ah, sbase + OFF_A + a_lane + kb);
#pragma unroll
            for (int ni2 = 0; ni2 < 2; ++ni2)
                ldm_x4(b4[ni2], sbase + OFF_BHI + b_lane4 + (uint32_t)(ni2 * 16) * RS + kb);
#pragma unroll
            for (int ni2 = 0; ni2 < 2; ++ni2)
#pragma unroll
                for (int half = 0; half < 2; ++half)
                    mma_f16(acc[ni2 * 2 + half], ah, b4[ni2] + half * 2);
#pragma unroll
            for (int ni2 = 0; ni2 < 2; ++ni2)
                ldm_x4(b4[ni2], sbase + OFF_BLO + b_lane4 + (uint32_t)(ni2 * 16) * RS + kb);
#pragma unroll
            for (int ni2 = 0; ni2 < 2; ++ni2)
#pragma unroll
                for (int half = 0; half < 2; ++half)
                    mma_f16(acc[ni2 * 2 + half], ah, b4[ni2] + half * 2);
        }
    }
    int rofs = lid >> 2, cofs = (lid & 3) * 2;
    int r0 = px0 + wid * 16 + rofs;
#pragma unroll
    for (int ni = 0; ni < 4; ++ni) {
        int c = ni * 8 + cofs;
        if (c < 18) {
            float2 bo = *(const float2*)(b_off + c);
            *(float2*)(g_off + r0 * 18 + c) =
                make_float2(acc[ni][0] + bo.x, acc[ni][1] + bo.y);
            *(float2*)(g_off + (r0 + 8) * 18 + c) =
                make_float2(acc[ni][2] + bo.x, acc[ni][3] + bo.y);
        }
    }
}

// ---------------- main: fp16 single-pass, 3-stage pipeline --------------------
// smem (XOR-swizzled 256B rows): A 3x32KB @0, B 3x32KB @98304. 192KB.
// barriers: FULL 1,2,3  FREE 4,5,6  (stage = k % 3)
#define A_ST(s)   ((uint32_t)(s) * 32768u)
#define B_ST(s)   (98304u + (uint32_t)(s) * 32768u)
#define WS_TOT    196608
#define RSF       132

struct Samp {
    uint2 r00, r01, r10, r11;    // fp16x4 per corner
    float w00, w01, w10, w11;
    uint32_t off;
};

__device__ __forceinline__ void samp_issueP(Samp& S, int p, int t, int ky, int kx,
                                            int px0, int lid) {
    int px = px0 + p;
    int b = px >> 14, h = (px >> 7) & 127, w = px & 127;
    float2 d = *(const float2*)(g_off + px * 18 + 2 * t);
    float ysf = (float)(h - 1 + ky) + d.x;
    float xsf = (float)(w - 1 + kx) + d.y;
    float fy = floorf(ysf), fx = floorf(xsf);
    float wy = ysf - fy, wx = xsf - fx;
    int iy0 = (int)fy, ix0 = (int)fx;
    int iy1 = iy0 + 1, ix1 = ix0 + 1;
    float my0 = (iy0 >= 0 && iy0 < H_) ? 1.f : 0.f;
    float my1 = (iy1 >= 0 && iy1 < H_) ? 1.f : 0.f;
    float mx0 = (ix0 >= 0 && ix0 < W_) ? 1.f : 0.f;
    float mx1 = (ix1 >= 0 && ix1 < W_) ? 1.f : 0.f;
    int cy0 = min(H_ - 1, max(0, iy0)), cy1 = min(H_ - 1, max(0, iy1));
    int cx0 = min(W_ - 1, max(0, ix0)), cx1 = min(W_ - 1, max(0, ix1));
    int base = b * HW_;
    int c4 = lid * 4;
    S.r00 = *(const uint2*)(g_x_h + (base + cy0 * W_ + cx0) * CI_ + c4);
    S.r01 = *(const uint2*)(g_x_h + (base + cy0 * W_ + cx1) * CI_ + c4);
    S.r10 = *(const uint2*)(g_x_h + (base + cy1 * W_ + cx0) * CI_ + c4);
    S.r11 = *(const uint2*)(g_x_h + (base + cy1 * W_ + cx1) * CI_ + c4);
    S.w00 = (1.f - wy) * (1.f - wx) * my0 * mx0;
    S.w01 = (1.f - wy) * wx * my0 * mx1;
    S.w10 = wy * (1.f - wx) * my1 * mx0;
    S.w11 = wy * wx * my1 * mx1;
    S.off = (uint32_t)p * 256u + (((((uint32_t)lid >> 1) ^ ((uint32_t)p & 7u)) << 4) | (((uint32_t)lid & 1u) << 3));
}

__device__ __forceinline__ void samp_storeP(char* sb, uint32_t abase, const Samp& S) {
    float2 a0 = __half22float2(*(const __half2*)&S.r00.x);
    float2 a1 = __half22float2(*(const __half2*)&S.r00.y);
    float2 b0 = __half22float2(*(const __half2*)&S.r01.x);
    float2 b1 = __half22float2(*(const __half2*)&S.r01.y);
    float2 c0 = __half22float2(*(const __half2*)&S.r10.x);
    float2 c1 = __half22float2(*(const __half2*)&S.r10.y);
    float2 d0 = __half22float2(*(const __half2*)&S.r11.x);
    float2 d1 = __half22float2(*(const __half2*)&S.r11.y);
    float4 s;
    s.x = fmaf(d0.x, S.w11, fmaf(c0.x, S.w10, fmaf(b0.x, S.w01, a0.x * S.w00)));
    s.y = fmaf(d0.y, S.w11, fmaf(c0.y, S.w10, fmaf(b0.y, S.w01, a0.y * S.w00)));
    s.z = fmaf(d1.x, S.w11, fmaf(c1.x, S.w10, fmaf(b1.x, S.w01, a1.x * S.w00)));
    s.w = fmaf(d1.y, S.w11, fmaf(c1.y, S.w10, fmaf(b1.y, S.w01, a1.y * S.w00)));
    uint2 hp;
    hp.x = f16x2(s.x, s.y);
    hp.y = f16x2(s.z, s.w);
    *(uint2*)(sb + abase + S.off) = hp;
}

__device__ __forceinline__ void copy_B_swz(uint32_t dstbase, const char* src, int ptid) {
#pragma unroll
    for (int j = 0; j < 8; ++j) {
        int c = ptid + j * 256;
        uint32_t row = (uint32_t)(c >> 4), c16 = (uint32_t)(c & 15);
        uint32_t dof = row * 256u + ((c16 ^ (row & 7u)) << 4);
        cp16(dstbase + dof, src + c * 16);
    }
}

__global__ void __launch_bounds__(512, 1) k_mainWS() {
    extern __shared__ char sb[];
    uint32_t sbase = smem_u32(sb);
    int tid = threadIdx.x;
    int wid = tid >> 5, lid = tid & 31;
    int px0 = blockIdx.x * 128;

    float acc[2][8][4];
#pragma unroll
    for (int mi = 0; mi < 2; ++mi)
#pragma unroll
        for (int nf = 0; nf < 8; ++nf)
#pragma unroll
            for (int j = 0; j < 4; ++j) acc[mi][nf][j] = 0.f;

    if (wid < 8) {
        // ================= CONSUMER =================
        int mw = wid >> 1, nw = wid & 1;
        uint32_t rA[2], rA7[2];
#pragma unroll
        for (int mi = 0; mi < 2; ++mi) {
            uint32_t r = (uint32_t)(mw * 32 + mi * 16 + (lid & 15));
            rA[mi] = r * 256u; rA7[mi] = r & 7u;
        }
        uint32_t chAh = (uint32_t)(lid >> 4);
        uint32_t rowp = (uint32_t)((lid & 7) | ((lid >> 4) << 3));
        uint32_t chBh = (uint32_t)((lid >> 3) & 1);
        uint32_t rB[4], rB7[4];
#pragma unroll
        for (int n = 0; n < 4; ++n) {
            uint32_t r = (uint32_t)(nw * 64 + n * 16) + rowp;
            rB[n] = r * 256u; rB7[n] = r & 7u;
        }

        int st = 0;
        for (int k = 0; k < 9; ++k) {
            BAR_SYNC(1 + st);          // stage[k] ready
            uint32_t Ast = sbase + A_ST(st);
            uint32_t Bst = sbase + B_ST(st);
#pragma unroll
            for (int s = 0; s < 8; ++s) {
                uint32_t cA = (uint32_t)(2 * s) + chAh;
                uint32_t cB = (uint32_t)(2 * s) + chBh;
                uint32_t ah[2][4], bh[4][4];
#pragma unroll
                for (int mi = 0; mi < 2; ++mi)
                    ldm_x4(ah[mi], Ast + rA[mi] + ((cA ^ rA7[mi]) << 4));
#pragma unroll
                for (int n = 0; n < 4; ++n)
                    ldm_x4(bh[n], Bst + rB[n] + ((cB ^ rB7[n]) << 4));
#pragma unroll
                for (int mi = 0; mi < 2; ++mi)
#pragma unroll
                    for (int nf = 0; nf < 8; ++nf)
                        mma_f16(acc[mi][nf], ah[mi], bh[nf >> 1] + (nf & 1) * 2);
            }
            BAR_ARRIVE(4 + st);        // stage free
            st = (st == 2) ? 0 : st + 1;
        }
    } else {
        // ================= PRODUCER =================
        int wp = wid - 8;
        int ptid = wp * 32 + lid;
        int st = 0;
        for (int k = 0; k < 9; ++k) {
            if (k >= 3) BAR_SYNC(4 + st);   // stage free
            copy_B_swz(sbase + B_ST(st), (const char*)g_wb + k * 32768, ptid);
            cp_commit();
            int ky = k / 3, kx = k - ky * 3;
            uint32_t Ast = A_ST(st);
            Samp S0, S1;
            samp_issueP(S0, wp, k, ky, kx, px0, lid);
#pragma unroll
            for (int i = 0; i < 16; ++i) {
                if ((i & 1) == 0) {
                    if (i < 15) samp_issueP(S1, (i + 1) * 8 + wp, k, ky, kx, px0, lid);
                    samp_storeP(sb, Ast, S0);
                } else {
                    if (i < 15) samp_issueP(S0, (i + 1) * 8 + wp, k, ky, kx, px0, lid);
                    samp_storeP(sb, Ast, S1);
                }
            }
            cp_wait0();
            __threadfence_block();
            BAR_ARRIVE(1 + st);             // stage full
            st = (st == 2) ? 0 : st + 1;
        }
    }

    __syncthreads();
    // ---- epilogue: consumers stage acc, all store + BN partials ----
    float* stg = (float*)sb;               // [128][RSF] = 67584 B
    if (wid < 8) {
        int mw = wid >> 1, nw = wid & 1;
        int rofs = lid >> 2, cofs = (lid & 3) * 2;
#pragma unroll
        for (int mi = 0; mi < 2; ++mi) {
            int r0 = mw * 32 + mi * 16 + rofs;
#pragma unroll
            for (int nf = 0; nf < 8; ++nf) {
                int co = nw * 64 + nf * 8 + cofs;
                *(float2*)(stg + r0 * RSF + co)       = make_float2(acc[mi][nf][0], acc[mi][nf][1]);
                *(float2*)(stg + (r0 + 8) * RSF + co) = make_float2(acc[mi][nf][2], acc[mi][nf][3]);
            }
        }
    }
    __syncthreads();
#pragma unroll
    for (int tt = 0; tt < 8; ++tt) {
        int idx = tid + tt * 512;
        int row = idx >> 5, c4 = (idx & 31) * 4;
        float4 v = *(const float4*)(stg + row * RSF + c4);
        *(float4*)(g_out + (px0 + row) * CO_ + c4) = v;
    }
    {
        int co = tid & 127, q = tid >> 7;
        float s = 0.f, qq = 0.f;
#pragma unroll
        for (int r = 0; r < 32; ++r) {
            float v = stg[(q * 32 + r) * RSF + co];
            s += v; qq = fmaf(v, v, qq);
        }
        float* reds = (float*)(sb + 98304);   // B region, past the stage
        float* redq = reds + 512;
        reds[q * 128 + co] = s;
        redq[q * 128 + co] = qq;
        __syncthreads();
        if (tid < 128) {
            float ss = reds[tid] + reds[128 + tid] + reds[256 + tid] + reds[384 + tid];
            float sq = redq[tid] + redq[128 + tid] + redq[256 + tid] + redq[384 + tid];
            atomicAdd(&g_sum[tid], (double)ss);
            atomicAdd(&g_sumsq[tid], (double)sq);
        }
    }
}

// ---------------- BN finalize ----------------
__global__ void k_fin(const float* __restrict__ gamma, const float* __restrict__ beta) {
    int c = threadIdx.x;
    if (c < CO_) {
        double N = (double)NPIX;
        double mean = g_sum[c] / N;
        double var  = g_sumsq[c] / N - mean * mean;
        float a = gamma[c] * rsqrtf((float)var + BN_EPS);
        g_scale[c] = a;
        g_shift[c] = beta[c] - (float)mean * a;
    }
}

// ---------------- apply BN + ReLU + transpose [px][co] -> NCHW ----------------
__global__ void k_apply(float* __restrict__ out) {
    __shared__ float sm[32][33];
    int b = blockIdx.z, co0 = blockIdx.y * 32, hw0 = blockIdx.x * 32;
    int tx = threadIdx.x, ty = threadIdx.y;
#pragma unroll
    for (int i = 0; i < 4; ++i) {
        int hw = hw0 + ty + i * 8;
        sm[ty + i * 8][tx] = g_out[(b * HW_ + hw) * CO_ + co0 + tx];
    }
    __syncthreads();
#pragma unroll
    for (int i = 0; i < 4; ++i) {
        int co = co0 + ty + i * 8;
        float a = g_scale[co], sh = g_shift[co];
        float v = fmaf(sm[tx][ty + i * 8], a, sh);
        out[(b * CO_ + co) * HW_ + hw0 + tx] = fmaxf(v, 0.f);
    }
}

// ---------------- launch ----------------
extern "C" void kernel_launch(void* const* d_in, const int* in_sizes, int n_in,
                              void* d_out, int out_size) {
    const float* x      = (const float*)d_in[0];
    const float* w_off  = (const float*)d_in[1];
    const float* b_off  = (const float*)d_in[2];
    const float* w_dcn  = (const float*)d_in[3];
    const float* gamma  = (const float*)d_in[4];
    const float* beta   = (const float*)d_in[5];
    float* out = (float*)d_out;

    cudaFuncSetAttribute(k_offT,   cudaFuncAttributeMaxDynamicSharedMemorySize, OFF_TOT);
    cudaFuncSetAttribute(k_mainWS, cudaFuncAttributeMaxDynamicSharedMemorySize, WS_TOT);

    dim3 tb(32, 8);
    k_tr_x<<<dim3(512, 4, B_), tb>>>(x);          // launch 0
    k_prep<<<576, 256>>>(w_dcn, w_off);           // launch 1
    k_offT<<<512, 256, OFF_TOT>>>(b_off);         // launch 2
    k_mainWS<<<512, 512, WS_TOT>>>();             // launch 3  <- ncu capture slot
    k_fin<<<1, 128>>>(gamma, beta);               // launch 4
    k_apply<<<dim3(512, 4, B_), tb>>>(out);       // launch 5
}

// round 16
// speedup vs baseline: 2.1302x; 1.2063x over previous
#include <cuda_runtime.h>
#include <cuda_fp16.h>
#include <cstdint>

#define B_   4
#define CI_  128
#define CO_  128
#define H_   128
#define W_   128
#define HW_  (H_*W_)
#define KK_  9
#define NPIX (B_*HW_)   // 65536
#define BN_EPS 0.001f

// ---------------- scratch ----------------
__device__ float  g_x_nhwc[NPIX*CI_];                       // [b][h][w][ci] fp32 (offT)
__device__ __align__(16) __half g_x_h[NPIX*CI_];            // same, fp16 (main gathers)
__device__ float  g_off[NPIX*18];                           // [px][18]
__device__ __align__(16) __half g_wb[KK_*CO_*CI_];          // main w fp16
__device__ __align__(16) __half g_wo_hi[KK_*32*CI_];        // offT w fp16 hi
__device__ __align__(16) __half g_wo_lo[KK_*32*CI_];        // offT w fp16 lo
__device__ __align__(16) int4  g_sa[KK_*NPIX];              // [tap][px] gather bases
__device__ __align__(16) uint4 g_sw[KK_*NPIX];              // [tap][px] weights (half2 dup x4)
__device__ float  g_out[NPIX*CO_];                          // [px][co]
__device__ double g_sum[CO_];
__device__ double g_sumsq[CO_];
__device__ float  g_scale[CO_];
__device__ float  g_shift[CO_];

__device__ __forceinline__ uint32_t smem_u32(const void* p) {
    uint32_t a;
    asm("{ .reg .u64 t; cvta.to.shared.u64 t, %1; cvt.u32.u64 %0, t; }" : "=r"(a) : "l"(p));
    return a;
}
__device__ __forceinline__ void ldm_x4(uint32_t* r, uint32_t a) {
    asm volatile("ldmatrix.sync.aligned.m8n8.x4.shared.b16 {%0,%1,%2,%3}, [%4];"
                 : "=r"(r[0]), "=r"(r[1]), "=r"(r[2]), "=r"(r[3]) : "r"(a));
}
__device__ __forceinline__ void mma_f16(float* c, const uint32_t* a, const uint32_t* b) {
    asm volatile(
        "mma.sync.aligned.m16n8k16.row.col.f32.f16.f16.f32 "
        "{%0,%1,%2,%3}, {%4,%5,%6,%7}, {%8,%9}, {%0,%1,%2,%3};"
        : "+f"(c[0]), "+f"(c[1]), "+f"(c[2]), "+f"(c[3])
        : "r"(a[0]), "r"(a[1]), "r"(a[2]), "r"(a[3]), "r"(b[0]), "r"(b[1]));
}
__device__ __forceinline__ uint32_t f16x2(float lo, float hi) {
    uint32_t d;
    asm("cvt.rn.f16x2.f32 %0, %1, %2;" : "=r"(d) : "f"(hi), "f"(lo));
    return d;
}
__device__ __forceinline__ uint32_t h2dup(float f) {
    uint32_t u = (uint32_t)__half_as_ushort(__float2half_rn(f));
    return u | (u << 16);
}
__device__ __forceinline__ void cp16(uint32_t dst, const void* src) {
    asm volatile("cp.async.cg.shared.global [%0], [%1], 16;" :: "r"(dst), "l"(src));
}
__device__ __forceinline__ void cp_commit() { asm volatile("cp.async.commit_group;" ::: "memory"); }
__device__ __forceinline__ void cp_wait0()  { asm volatile("cp.async.wait_group 0;" ::: "memory"); }
#define BAR_SYNC(id)   asm volatile("bar.sync %0, 512;"   :: "r"(id) : "memory")
#define BAR_ARRIVE(id) asm volatile("bar.arrive %0, 512;" :: "r"(id) : "memory")

// ---------------- x: NCHW -> NHWC (fp32 + fp16 copies) ----------------
__global__ void k_tr_x(const float* __restrict__ x) {
    __shared__ float sm[32][33];
    int b = blockIdx.z, ci0 = blockIdx.y * 32, hw0 = blockIdx.x * 32;
    int tx = threadIdx.x, ty = threadIdx.y;
#pragma unroll
    for (int i = 0; i < 4; ++i) {
        int ci = ci0 + ty + i * 8;
        sm[ty + i * 8][tx] = x[(b * CI_ + ci) * HW_ + hw0 + tx];
    }
    __syncthreads();
#pragma unroll
    for (int i = 0; i < 4; ++i) {
        int hw = hw0 + ty + i * 8;
        float v = sm[tx][ty + i * 8];
        int o = (b * HW_ + hw) * CI_ + ci0 + tx;
        g_x_nhwc[o] = v;
        g_x_h[o] = __float2half_rn(v);
    }
}

// ---------------- prep: BN zero + weight transforms ----------------
__global__ void k_prep(const float* __restrict__ w_dcn, const float* __restrict__ w_off) {
    int idx = blockIdx.x * 256 + threadIdx.x;
    if (idx < 128) { g_sum[idx] = 0.0; g_sumsq[idx] = 0.0; }
    if (idx < KK_ * CO_ * CI_) {
        int tap = idx >> 14;
        int r   = idx & 16383;
        int co  = r >> 7;
        int ci  = r & 127;
        float w = w_dcn[(co * CI_ + ci) * KK_ + tap];
        g_wb[idx] = __float2half_rn(w);
    }
    if (idx < KK_ * 32 * CI_) {
        int tap = idx >> 12;
        int r   = idx & 4095;
        int co  = r >> 7;
        int ci  = r & 127;
        float w = (co < 18) ? w_off[(co * CI_ + ci) * KK_ + tap] : 0.f;
        __half hi = __float2half_rn(w);
        __half lo = __float2half_rn(w - __half2float(hi));
        g_wo_hi[idx] = hi;
        g_wo_lo[idx] = lo;
    }
}

#define RS 272   // padded stride for k_offT

// ---------------- offset conv + sampling-param epilogue -----------------------
#define OFF_A   0
#define OFF_BHI 34816
#define OFF_BLO 43520
#define OFF_TOT 52224

__global__ void __launch_bounds__(256, 2) k_offT(const float* __restrict__ b_off) {
    extern __shared__ char sb[];
    uint32_t sbase = smem_u32(sb);
    int tid = threadIdx.x;
    int wid = tid >> 5, lid = tid & 31;
    int px0 = blockIdx.x * 128;

    float acc[4][4];
#pragma unroll
    for (int ni = 0; ni < 4; ++ni)
#pragma unroll
        for (int j = 0; j < 4; ++j) acc[ni][j] = 0.f;

    uint32_t a_lane = (uint32_t)(wid * 16 + (lid & 15)) * RS + ((lid >> 4) << 4);
    uint32_t b_lane4 = (uint32_t)((lid & 7) | ((lid >> 4) << 3)) * RS + (((lid >> 3) & 1) << 4);

    for (int k = 0; k < 9; ++k) {
        int ky = k / 3, kx = k - ky * 3;
        __syncthreads();
#pragma unroll
        for (int t = 0; t < 2; ++t) {
            int e = tid + t * 256;
            int row = e >> 4, c16 = e & 15;
            *(uint4*)(sb + OFF_BHI + row * RS + c16 * 16) =
                *(const uint4*)(g_wo_hi + k * 4096 + row * 128 + c16 * 8);
            *(uint4*)(sb + OFF_BLO + row * RS + c16 * 16) =
                *(const uint4*)(g_wo_lo + k * 4096 + row * 128 + c16 * 8);
        }
#pragma unroll 2
        for (int i = 0; i < 16; ++i) {
            int p = i * 8 + wid;
            int px = px0 + p;
            int b = px >> 14, h = (px >> 7) & 127, w = px & 127;
            int y = h - 1 + ky, xx = w - 1 + kx;
            uint2 hp = make_uint2(0u, 0u);
            if ((unsigned)y < (unsigned)H_ && (unsigned)xx < (unsigned)W_) {
                float4 v = *(const float4*)(g_x_nhwc + ((b * H_ + y) * W_ + xx) * CI_ + lid * 4);
                hp.x = f16x2(v.x, v.y);
                hp.y = f16x2(v.z, v.w);
            }
            *(uint2*)(sb + OFF_A + (uint32_t)p * RS + (uint32_t)lid * 8) = hp;
        }
        __syncthreads();
#pragma unroll
        for (int ks = 0; ks < 8; ++ks) {
            uint32_t kb = (uint32_t)ks * 32;
            uint32_t ah[4], b4[2][4];
            ldm_x4(ah, sbase + OFF_A + a_lane + kb);
#pragma unroll
            for (int ni2 = 0; ni2 < 2; ++ni2)
                ldm_x4(b4[ni2], sbase + OFF_BHI + b_lane4 + (uint32_t)(ni2 * 16) * RS + kb);
#pragma unroll
            for (int ni2 = 0; ni2 < 2; ++ni2)
#pragma unroll
                for (int half = 0; half < 2; ++half)
                    mma_f16(acc[ni2 * 2 + half], ah, b4[ni2] + half * 2);
#pragma unroll
            for (int ni2 = 0; ni2 < 2; ++ni2)
                ldm_x4(b4[ni2], sbase + OFF_BLO + b_lane4 + (uint32_t)(ni2 * 16) * RS + kb);
#pragma unroll
            for (int ni2 = 0; ni2 < 2; ++ni2)
#pragma unroll
                for (int half = 0; half < 2; ++half)
                    mma_f16(acc[ni2 * 2 + half], ah, b4[ni2] + half * 2);
        }
    }
    int rofs = lid >> 2, cofs = (lid & 3) * 2;
    int r0 = px0 + wid * 16 + rofs;
#pragma unroll
    for (int ni = 0; ni < 4; ++ni) {
        int c = ni * 8 + cofs;
        if (c < 18) {
            float2 bo = *(const float2*)(b_off + c);
            *(float2*)(g_off + r0 * 18 + c) =
                make_float2(acc[ni][0] + bo.x, acc[ni][1] + bo.y);
            *(float2*)(g_off + (r0 + 8) * 18 + c) =
                make_float2(acc[ni][2] + bo.x, acc[ni][3] + bo.y);
        }
    }

    // ---- epilogue: sampling params for this block's 128 px x 9 taps ----
    __syncthreads();   // g_off writes visible block-wide
    for (int e = tid; e < 128 * 9; e += 256) {
        int p = e / 9;
        int t = e - p * 9;
        int px = px0 + p;
        int b = px >> 14, h = (px >> 7) & 127, w = px & 127;
        int ky = t / 3, kx = t - ky * 3;
        float2 d = *(const float2*)(g_off + px * 18 + 2 * t);
        float ysf = (float)(h - 1 + ky) + d.x;
        float xsf = (float)(w - 1 + kx) + d.y;
        float fy = floorf(ysf), fx = floorf(xsf);
        float wy = ysf - fy, wx = xsf - fx;
        int iy0 = (int)fy, ix0 = (int)fx;
        int iy1 = iy0 + 1, ix1 = ix0 + 1;
        float my0 = (iy0 >= 0 && iy0 < H_) ? 1.f : 0.f;
        float my1 = (iy1 >= 0 && iy1 < H_) ? 1.f : 0.f;
        float mx0 = (ix0 >= 0 && ix0 < W_) ? 1.f : 0.f;
        float mx1 = (ix1 >= 0 && ix1 < W_) ? 1.f : 0.f;
        int cy0 = min(H_ - 1, max(0, iy0)), cy1 = min(H_ - 1, max(0, iy1));
        int cx0 = min(W_ - 1, max(0, ix0)), cx1 = min(W_ - 1, max(0, ix1));
        int base = b * HW_;
        int4 a;
        a.x = (base + cy0 * W_ + cx0) * CI_;
        a.y = (base + cy0 * W_ + cx1) * CI_;
        a.z = (base + cy1 * W_ + cx0) * CI_;
        a.w = (base + cy1 * W_ + cx1) * CI_;
        uint4 wv;
        wv.x = h2dup((1.f - wy) * (1.f - wx) * my0 * mx0);
        wv.y = h2dup((1.f - wy) * wx * my0 * mx1);
        wv.z = h2dup(wy * (1.f - wx) * my1 * mx0);
        wv.w = h2dup(wy * wx * my1 * mx1);
        int o = (t << 16) + px;
        g_sa[o] = a;
        g_sw[o] = wv;
    }
}

// ---------------- main: fp16 single-pass, 3-stage, param-fed producer ---------
// smem (XOR-swizzled 256B rows): A 3x32KB @0, B 3x32KB @98304. 192KB.
// barriers: FULL 1,2,3  FREE 4,5,6  (stage = k % 3)
#define A_ST(s)   ((uint32_t)(s) * 32768u)
#define B_ST(s)   (98304u + (uint32_t)(s) * 32768u)
#define WS_TOT    196608
#define RSF       132

struct SG {
    uint2 r00, r01, r10, r11;   // gathered fp16x4 per corner
    uint4 w;                    // half2-dup weights
    uint32_t off;
};

__device__ __forceinline__ void gatherP(SG& G, const int4 a, const uint4 w, int p, int lid) {
    int c4 = lid * 4;
    G.r00 = *(const uint2*)(g_x_h + a.x + c4);
    G.r01 = *(const uint2*)(g_x_h + a.y + c4);
    G.r10 = *(const uint2*)(g_x_h + a.z + c4);
    G.r11 = *(const uint2*)(g_x_h + a.w + c4);
    G.w = w;
    G.off = (uint32_t)p * 256u + (((((uint32_t)lid >> 1) ^ ((uint32_t)p & 7u)) << 4) | (((uint32_t)lid & 1u) << 3));
}

__device__ __forceinline__ void storeG(char* sb, uint32_t abase, const SG& G) {
    __half2 w0 = *(const __half2*)&G.w.x;
    __half2 w1 = *(const __half2*)&G.w.y;
    __half2 w2 = *(const __half2*)&G.w.z;
    __half2 w3 = *(const __half2*)&G.w.w;
    __half2 s0 = __hmul2(*(const __half2*)&G.r00.x, w0);
    s0 = __hfma2(*(const __half2*)&G.r01.x, w1, s0);
    s0 = __hfma2(*(const __half2*)&G.r10.x, w2, s0);
    s0 = __hfma2(*(const __half2*)&G.r11.x, w3, s0);
    __half2 s1 = __hmul2(*(const __half2*)&G.r00.y, w0);
    s1 = __hfma2(*(const __half2*)&G.r01.y, w1, s1);
    s1 = __hfma2(*(const __half2*)&G.r10.y, w2, s1);
    s1 = __hfma2(*(const __half2*)&G.r11.y, w3, s1);
    uint2 o;
    o.x = *(const uint32_t*)&s0;
    o.y = *(const uint32_t*)&s1;
    *(uint2*)(sb + abase + G.off) = o;
}

__device__ __forceinline__ void copy_B_swz(uint32_t dstbase, const char* src, int ptid) {
#pragma unroll
    for (int j = 0; j < 8; ++j) {
        int c = ptid + j * 256;
        uint32_t row = (uint32_t)(c >> 4), c16 = (uint32_t)(c & 15);
        uint32_t dof = row * 256u + ((c16 ^ (row & 7u)) << 4);
        cp16(dstbase + dof, src + c * 16);
    }
}

__global__ void __launch_bounds__(512, 1) k_mainWS() {
    extern __shared__ char sb[];
    uint32_t sbase = smem_u32(sb);
    int tid = threadIdx.x;
    int wid = tid >> 5, lid = tid & 31;
    int px0 = blockIdx.x * 128;

    float acc[2][8][4];
#pragma unroll
    for (int mi = 0; mi < 2; ++mi)
#pragma unroll
        for (int nf = 0; nf < 8; ++nf)
#pragma unroll
            for (int j = 0; j < 4; ++j) acc[mi][nf][j] = 0.f;

    if (wid < 8) {
        // ================= CONSUMER =================
        int mw = wid >> 1, nw = wid & 1;
        uint32_t rA[2], rA7[2];
#pragma unroll
        for (int mi = 0; mi < 2; ++mi) {
            uint32_t r = (uint32_t)(mw * 32 + mi * 16 + (lid & 15));
            rA[mi] = r * 256u; rA7[mi] = r & 7u;
        }
        uint32_t chAh = (uint32_t)(lid >> 4);
        uint32_t rowp = (uint32_t)((lid & 7) | ((lid >> 4) << 3));
        uint32_t chBh = (uint32_t)((lid >> 3) & 1);
        uint32_t rB[4], rB7[4];
#pragma unroll
        for (int n = 0; n < 4; ++n) {
            uint32_t r = (uint32_t)(nw * 64 + n * 16) + rowp;
            rB[n] = r * 256u; rB7[n] = r & 7u;
        }

        int st = 0;
        for (int k = 0; k < 9; ++k) {
            BAR_SYNC(1 + st);          // stage[k] ready
            uint32_t Ast = sbase + A_ST(st);
            uint32_t Bst = sbase + B_ST(st);
#pragma unroll
            for (int s = 0; s < 8; ++s) {
                uint32_t cA = (uint32_t)(2 * s) + chAh;
                uint32_t cB = (uint32_t)(2 * s) + chBh;
                uint32_t ah[2][4], bh[4][4];
#pragma unroll
                for (int mi = 0; mi < 2; ++mi)
                    ldm_x4(ah[mi], Ast + rA[mi] + ((cA ^ rA7[mi]) << 4));
#pragma unroll
                for (int n = 0; n < 4; ++n)
                    ldm_x4(bh[n], Bst + rB[n] + ((cB ^ rB7[n]) << 4));
#pragma unroll
                for (int mi = 0; mi < 2; ++mi)
#pragma unroll
                    for (int nf = 0; nf < 8; ++nf)
                        mma_f16(acc[mi][nf], ah[mi], bh[nf >> 1] + (nf & 1) * 2);
            }
            BAR_ARRIVE(4 + st);        // stage free
            st = (st == 2) ? 0 : st + 1;
        }
    } else {
        // ================= PRODUCER (param-fed) =================
        int wp = wid - 8;
        int ptid = wp * 32 + lid;
        int st = 0;
        for (int k = 0; k < 9; ++k) {
            if (k >= 3) BAR_SYNC(4 + st);   // stage free
            copy_B_swz(sbase + B_ST(st), (const char*)g_wb + k * 32768, ptid);
            cp_commit();
            uint32_t Ast = A_ST(st);
            int pb = (k << 16) + px0 + wp;
            int4  pa0 = g_sa[pb],      pa1 = g_sa[pb + 8];
            uint4 pw0 = g_sw[pb],      pw1 = g_sw[pb + 8];
            SG G0, G1;
            gatherP(G0, pa0, pw0, wp, lid);
            pa0 = g_sa[pb + 16]; pw0 = g_sw[pb + 16];
            gatherP(G1, pa1, pw1, 8 + wp, lid);
            pa1 = g_sa[pb + 24]; pw1 = g_sw[pb + 24];
#pragma unroll
            for (int i = 0; i < 16; ++i) {
                if ((i & 1) == 0) {
                    storeG(sb, Ast, G0);
                    if (i + 2 < 16) gatherP(G0, pa0, pw0, (i + 2) * 8 + wp, lid);
                    if (i + 4 < 16) { pa0 = g_sa[pb + (i + 4) * 8]; pw0 = g_sw[pb + (i + 4) * 8]; }
                } else {
                    storeG(sb, Ast, G1);
                    if (i + 2 < 16) gatherP(G1, pa1, pw1, (i + 2) * 8 + wp, lid);
                    if (i + 4 < 16) { pa1 = g_sa[pb + (i + 4) * 8]; pw1 = g_sw[pb + (i + 4) * 8]; }
                }
            }
            cp_wait0();
            __threadfence_block();
            BAR_ARRIVE(1 + st);             // stage full
            st = (st == 2) ? 0 : st + 1;
        }
    }

    __syncthreads();
    // ---- epilogue: consumers stage acc, all store + BN partials ----
    float* stg = (float*)sb;
    if (wid < 8) {
        int mw = wid >> 1, nw = wid & 1;
        int rofs = lid >> 2, cofs = (lid & 3) * 2;
#pragma unroll
        for (int mi = 0; mi < 2; ++mi) {
            int r0 = mw * 32 + mi * 16 + rofs;
#pragma unroll
            for (int nf = 0; nf < 8; ++nf) {
                int co = nw * 64 + nf * 8 + cofs;
                *(float2*)(stg + r0 * RSF + co)       = make_float2(acc[mi][nf][0], acc[mi][nf][1]);
                *(float2*)(stg + (r0 + 8) * RSF + co) = make_float2(acc[mi][nf][2], acc[mi][nf][3]);
            }
        }
    }
    __syncthreads();
#pragma unroll
    for (int tt = 0; tt < 8; ++tt) {
        int idx = tid + tt * 512;
        int row = idx >> 5, c4 = (idx & 31) * 4;
        float4 v = *(const float4*)(stg + row * RSF + c4);
        *(float4*)(g_out + (px0 + row) * CO_ + c4) = v;
    }
    {
        int co = tid & 127, q = tid >> 7;
        float s = 0.f, qq = 0.f;
#pragma unroll
        for (int r = 0; r < 32; ++r) {
            float v = stg[(q * 32 + r) * RSF + co];
            s += v; qq = fmaf(v, v, qq);
        }
        float* reds = (float*)(sb + 98304);
        float* redq = reds + 512;
        reds[q * 128 + co] = s;
        redq[q * 128 + co] = qq;
        __syncthreads();
        if (tid < 128) {
            float ss = reds[tid] + reds[128 + tid] + reds[256 + tid] + reds[384 + tid];
            float sq = redq[tid] + redq[128 + tid] + redq[256 + tid] + redq[384 + tid];
            atomicAdd(&g_sum[tid], (double)ss);
            atomicAdd(&g_sumsq[tid], (double)sq);
        }
    }
}

// ---------------- BN finalize ----------------
__global__ void k_fin(const float* __restrict__ gamma, const float* __restrict__ beta) {
    int c = threadIdx.x;
    if (c < CO_) {
        double N = (double)NPIX;
        double mean = g_sum[c] / N;
        double var  = g_sumsq[c] / N - mean * mean;
        float a = gamma[c] * rsqrtf((float)var + BN_EPS);
        g_scale[c] = a;
        g_shift[c] = beta[c] - (float)mean * a;
    }
}

// ---------------- apply BN + ReLU + transpose [px][co] -> NCHW ----------------
__global__ void k_apply(float* __restrict__ out) {
    __shared__ float sm[32][33];
    int b = blockIdx.z, co0 = blockIdx.y * 32, hw0 = blockIdx.x * 32;
    int tx = threadIdx.x, ty = threadIdx.y;
#pragma unroll
    for (int i = 0; i < 4; ++i) {
        int hw = hw0 + ty + i * 8;
        sm[ty + i * 8][tx] = g_out[(b * HW_ + hw) * CO_ + co0 + tx];
    }
    __syncthreads();
#pragma unroll
    for (int i = 0; i < 4; ++i) {
        int co = co0 + ty + i * 8;
        float a = g_scale[co], sh = g_shift[co];
        float v = fmaf(sm[tx][ty + i * 8], a, sh);
        out[(b * CO_ + co) * HW_ + hw0 + tx] = fmaxf(v, 0.f);
    }
}

// ---------------- launch ----------------
extern "C" void kernel_launch(void* const* d_in, const int* in_sizes, int n_in,
                              void* d_out, int out_size) {
    const float* x      = (const float*)d_in[0];
    const float* w_off  = (const float*)d_in[1];
    const float* b_off  = (const float*)d_in[2];
    const float* w_dcn  = (const float*)d_in[3];
    const float* gamma  = (const float*)d_in[4];
    const float* beta   = (const float*)d_in[5];
    float* out = (float*)d_out;

    cudaFuncSetAttribute(k_offT,   cudaFuncAttributeMaxDynamicSharedMemorySize, OFF_TOT);
    cudaFuncSetAttribute(k_mainWS, cudaFuncAttributeMaxDynamicSharedMemorySize, WS_TOT);

    dim3 tb(32, 8);
    k_tr_x<<<dim3(512, 4, B_), tb>>>(x);          // launch 0
    k_prep<<<576, 256>>>(w_dcn, w_off);           // launch 1
    k_offT<<<512, 256, OFF_TOT>>>(b_off);         // launch 2 (now also emits params)
    k_mainWS<<<512, 512, WS_TOT>>>();             // launch 3  <- ncu capture slot
    k_fin<<<1, 128>>>(gamma, beta);               // launch 4
    k_apply<<<dim3(512, 4, B_), tb>>>(out);       // launch 5
}